// round 2
// baseline (speedup 1.0000x reference)
#include <cuda_runtime.h>
#include <math.h>
#include <stdint.h>

#define BB 8
#define TT 90
#define HIMG 290
#define WIMG 180
#define PS 10
#define NWP 18
#define NP 522
#define PD 100
#define NV 94
#define KVIS 24
#define LL 2160
#define DD 256
#define NHEAD 8
#define DH 32
#define NLAYERS 6
#define DFF 1024
#define MM (BB*LL)   /* 17280 */

// ---------------- scratch (no cudaMalloc allowed) ----------------
__device__ float g_x[MM*DD];
__device__ float g_qkv[MM*3*DD];
__device__ float g_att[MM*DD];
__device__ float g_y[MM*DD];
__device__ float g_ff[MM*DFF];
__device__ int   g_tokv[MM];

// ---------------- token list: visible v per (b,t), in order ----------------
// patch_mask is a JAX bool array; the harness may hand it to us as int32,
// float32, or raw bytes. Detect the representation from the first row:
//   int32:   all words in {0,1} (bool-bytes at ~95% ones-density cannot fake this)
//   float32: all words in {0.0f, 1.0f} (int 1 reads as denormal, bool bytes as junk)
//   else:    1 byte per element
__global__ void build_vis_kernel(const void* __restrict__ mask_raw,
                                 const int* __restrict__ valid_idx)
{
    int bt = blockIdx.x*blockDim.x + threadIdx.x;
    if (bt >= BB*TT) return;

    const int*   mi = (const int*)mask_raw;
    const float* mf = (const float*)mask_raw;
    const unsigned char* mb = (const unsigned char*)mask_raw;

    // dtype detection on row 0 (each thread redundantly; broadcast-cached, cheap)
    int is_int = 1;
    for (int j = 0; j < NP; j++) {
        int w = mi[j];
        if (w != 0 && w != 1) { is_int = 0; break; }
    }
    int is_float = 0;
    if (!is_int) {
        is_float = 1;
        for (int j = 0; j < NP; j++) {
            float w = mf[j];
            if (w != 0.0f && w != 1.0f) { is_float = 0; break; }
        }
    }

    int base = bt*KVIS;
    int cnt = 0;
    for (int v = 0; v < NV; v++) {
        int idx = bt*NP + valid_idx[v];
        int masked;
        if (is_int)        masked = (mi[idx] != 0);
        else if (is_float) masked = (mf[idx] != 0.0f);
        else               masked = (mb[idx] != 0);
        if (!masked) {                    // False == visible
            if (cnt < KVIS) g_tokv[base+cnt] = v;
            cnt++;
        }
    }
}

// ---------------- patchify + patch embed + pos encodings ----------------
// 16 tokens per block, 256 threads (one per output channel d).
__global__ void __launch_bounds__(256) embed_kernel(
    const float* __restrict__ img, const int* __restrict__ valid_idx,
    const float* __restrict__ Wpe, const float* __restrict__ bpe,
    const float* __restrict__ spos)
{
    __shared__ float pix[16][PD];
    __shared__ float wsm[DD][27];        // 25-wide k chunk, pad 27 (odd stride)
    __shared__ int sm_v[16], sm_t[16], sm_off[16];
    int tid = threadIdx.x;
    int m0 = blockIdx.x * 16;
    if (tid < 16) {
        int m = m0 + tid;
        int b = m / LL;
        int l = m - b*LL;
        int t = l / KVIS;
        int v = g_tokv[m];
        int patch = valid_idx[v];
        int hp = patch / NWP, wp = patch - hp*NWP;
        sm_v[tid] = v; sm_t[tid] = t;
        sm_off[tid] = ((b*TT + t)*HIMG + hp*PS)*WIMG + wp*PS;
    }
    __syncthreads();
    for (int j = tid; j < 16*PD; j += 256) {
        int tok = j / PD, pd = j - tok*PD;
        int ph = pd / PS, pw = pd - ph*PS;
        pix[tok][pd] = img[sm_off[tok] + ph*WIMG + pw];
    }
    float acc[16];
    #pragma unroll
    for (int i = 0; i < 16; i++) acc[i] = 0.f;
    for (int k0 = 0; k0 < PD; k0 += 25) {
        __syncthreads();
        for (int j = tid; j < DD*25; j += 256) {
            int dd = j / 25, kk = j - dd*25;
            wsm[dd][kk] = Wpe[dd*PD + k0 + kk];
        }
        __syncthreads();
        #pragma unroll
        for (int kk = 0; kk < 25; kk++) {
            float w = wsm[tid][kk];
            #pragma unroll
            for (int tok = 0; tok < 16; tok++)
                acc[tok] = fmaf(w, pix[tok][k0+kk], acc[tok]);
        }
    }
    int d = tid;
    // sinusoidal PE: freq = exp(2i * (-ln(10000)/D)), 2i = d & ~1
    float freq = expf((float)(d & ~1) * (-9.210340371976184f / 256.f));
    float pb = bpe[d];
    #pragma unroll
    for (int tok = 0; tok < 16; tok++) {
        float val = (float)sm_t[tok] * freq;
        float pe = (d & 1) ? cosf(val) : sinf(val);
        g_x[(m0+tok)*DD + d] = acc[tok] + pb + spos[sm_v[tok]*DD + d] + pe;
    }
}

// ---------------- fp32 SGEMM: C[m,n] = sum_k A[m,k]*W[n,k] + bias[n] --------
// BM=BN=128, BK=16, 256 threads, 8x8 per-thread tile. All dims exact multiples.
__global__ void __launch_bounds__(256,2) gemm_kernel(
    const float* __restrict__ A, const float* __restrict__ W,
    const float* __restrict__ bias, float* __restrict__ C,
    int Ndim, int Kdim, int relu)
{
    __shared__ float As[16][132];
    __shared__ float Ws[16][132];
    int tid = threadIdx.x;
    int m0 = blockIdx.x * 128;
    int n0 = blockIdx.y * 128;
    int lr = tid >> 2;             // 0..63
    int lc = (tid & 3) << 2;       // 0,4,8,12
    const float* Ap = A + (m0 + lr)*Kdim + lc;
    const float* Wp = W + (n0 + lr)*Kdim + lc;
    int tx = tid & 15, ty = tid >> 4;
    float acc[8][8];
    #pragma unroll
    for (int i=0;i<8;i++)
        #pragma unroll
        for (int j=0;j<8;j++) acc[i][j]=0.f;

    for (int k0 = 0; k0 < Kdim; k0 += 16) {
        float4 a0 = *(const float4*)(Ap + k0);
        float4 a1 = *(const float4*)(Ap + 64*Kdim + k0);
        float4 w0 = *(const float4*)(Wp + k0);
        float4 w1 = *(const float4*)(Wp + 64*Kdim + k0);
        __syncthreads();
        As[lc+0][lr]=a0.x; As[lc+1][lr]=a0.y; As[lc+2][lr]=a0.z; As[lc+3][lr]=a0.w;
        As[lc+0][lr+64]=a1.x; As[lc+1][lr+64]=a1.y; As[lc+2][lr+64]=a1.z; As[lc+3][lr+64]=a1.w;
        Ws[lc+0][lr]=w0.x; Ws[lc+1][lr]=w0.y; Ws[lc+2][lr]=w0.z; Ws[lc+3][lr]=w0.w;
        Ws[lc+0][lr+64]=w1.x; Ws[lc+1][lr+64]=w1.y; Ws[lc+2][lr+64]=w1.z; Ws[lc+3][lr+64]=w1.w;
        __syncthreads();
        #pragma unroll
        for (int kk=0; kk<16; kk++) {
            float a[8], w[8];
            *(float4*)(a)   = *(const float4*)(&As[kk][ty*8]);
            *(float4*)(a+4) = *(const float4*)(&As[kk][ty*8+4]);
            *(float4*)(w)   = *(const float4*)(&Ws[kk][tx*8]);
            *(float4*)(w+4) = *(const float4*)(&Ws[kk][tx*8+4]);
            #pragma unroll
            for (int i=0;i<8;i++)
                #pragma unroll
                for (int j=0;j<8;j++)
                    acc[i][j] = fmaf(a[i], w[j], acc[i][j]);
        }
    }
    float bn[8];
    #pragma unroll
    for (int j=0;j<8;j++) bn[j] = bias[n0 + tx*8 + j];
    #pragma unroll
    for (int i=0;i<8;i++) {
        float vv[8];
        #pragma unroll
        for (int j=0;j<8;j++) {
            float t = acc[i][j] + bn[j];
            if (relu) t = fmaxf(t, 0.f);
            vv[j] = t;
        }
        float* Cp = C + (m0 + ty*8 + i)*Ndim + n0 + tx*8;
        *(float4*)(Cp)   = make_float4(vv[0],vv[1],vv[2],vv[3]);
        *(float4*)(Cp+4) = make_float4(vv[4],vv[5],vv[6],vv[7]);
    }
}

// ---------------- dense flash-style attention, fp32 ----------------
// grid (34, B*NHEAD). BQ=BK=64. 256 thr: S frag 4x4 (tx=cols, ty=rows),
// O frag 4 rows x 2 cols. P staged through smem.
__global__ void __launch_bounds__(256) attn_kernel(const float* __restrict__ qkv,
                                                   float* __restrict__ out)
{
    __shared__ float Qs[64][DH+1];
    __shared__ float Ks[64][DH+1];
    __shared__ float Vs[64][DH+1];
    __shared__ float Ps[64][65];
    int tid = threadIdx.x;
    int q0 = blockIdx.x * 64;
    int b = blockIdx.y >> 3;
    int h = blockIdx.y & 7;
    const float* base = qkv + b*LL*3*DD;
    for (int j = tid; j < 64*DH; j += 256) {
        int r = j >> 5, d = j & 31;
        int qrow = q0 + r;
        Qs[r][d] = (qrow < LL) ? base[qrow*3*DD + h*DH + d] : 0.f;
    }
    int tx = tid & 15, ty = tid >> 4;
    int R = ty*4, Ccol = tx*4, c0 = tx*2;
    float o0[4], o1[4], mrow[4], lrow[4];
    #pragma unroll
    for (int i=0;i<4;i++){ o0[i]=0.f; o1[i]=0.f; mrow[i]=-1e30f; lrow[i]=0.f; }
    const float scale = 0.17677669529663687f;  // 1/sqrt(32)

    for (int kt = 0; kt < (LL+63)/64; kt++) {
        int k0 = kt*64;
        __syncthreads();                        // protect Ks/Vs/Ps reuse
        for (int j = tid; j < 64*DH; j += 256) {
            int r = j >> 5, d = j & 31;
            int krow = k0 + r;
            float kv=0.f, vv=0.f;
            if (krow < LL) {
                int off = krow*3*DD + h*DH + d;
                kv = base[off + DD];
                vv = base[off + 2*DD];
            }
            Ks[r][d]=kv; Vs[r][d]=vv;
        }
        __syncthreads();
        float s[4][4];
        #pragma unroll
        for (int i=0;i<4;i++)
            #pragma unroll
            for (int j=0;j<4;j++) s[i][j]=0.f;
        #pragma unroll
        for (int kk=0; kk<DH; kk++) {
            float a[4], bv[4];
            #pragma unroll
            for (int i=0;i<4;i++) a[i]=Qs[R+i][kk];
            #pragma unroll
            for (int j=0;j<4;j++) bv[j]=Ks[Ccol+j][kk];
            #pragma unroll
            for (int i=0;i<4;i++)
                #pragma unroll
                for (int j=0;j<4;j++)
                    s[i][j] = fmaf(a[i], bv[j], s[i][j]);
        }
        #pragma unroll
        for (int i=0;i<4;i++) {
            #pragma unroll
            for (int j=0;j<4;j++) {
                float v = s[i][j]*scale;
                s[i][j] = (k0 + Ccol + j < LL) ? v : -1e30f;
            }
            float mx = fmaxf(fmaxf(s[i][0],s[i][1]), fmaxf(s[i][2],s[i][3]));
            mx = fmaxf(mx, __shfl_xor_sync(0xffffffffu, mx, 1));
            mx = fmaxf(mx, __shfl_xor_sync(0xffffffffu, mx, 2));
            mx = fmaxf(mx, __shfl_xor_sync(0xffffffffu, mx, 4));
            mx = fmaxf(mx, __shfl_xor_sync(0xffffffffu, mx, 8));
            float mnew = fmaxf(mrow[i], mx);
            float fac = __expf(mrow[i] - mnew);
            float rs = 0.f;
            #pragma unroll
            for (int j=0;j<4;j++) {
                float p = __expf(s[i][j] - mnew);
                s[i][j] = p;
                rs += p;
            }
            rs += __shfl_xor_sync(0xffffffffu, rs, 1);
            rs += __shfl_xor_sync(0xffffffffu, rs, 2);
            rs += __shfl_xor_sync(0xffffffffu, rs, 4);
            rs += __shfl_xor_sync(0xffffffffu, rs, 8);
            lrow[i] = lrow[i]*fac + rs;
            mrow[i] = mnew;
            o0[i]*=fac; o1[i]*=fac;
            Ps[R+i][Ccol+0]=s[i][0];
            Ps[R+i][Ccol+1]=s[i][1];
            Ps[R+i][Ccol+2]=s[i][2];
            Ps[R+i][Ccol+3]=s[i][3];
        }
        __syncthreads();
        #pragma unroll 4
        for (int k=0;k<64;k++) {
            float v0 = Vs[k][c0], v1 = Vs[k][c0+1];
            #pragma unroll
            for (int i=0;i<4;i++) {
                float p = Ps[R+i][k];
                o0[i] = fmaf(p, v0, o0[i]);
                o1[i] = fmaf(p, v1, o1[i]);
            }
        }
    }
    #pragma unroll
    for (int i=0;i<4;i++) {
        int qrow = q0 + R + i;
        if (qrow < LL) {
            float inv = 1.f / lrow[i];
            int o = (b*LL + qrow)*DD + h*DH + c0;
            out[o]   = o0[i]*inv;
            out[o+1] = o1[i]*inv;
        }
    }
}

// ---------------- residual add + LayerNorm (two-pass, exact) ----------------
__global__ void __launch_bounds__(256) add_ln_kernel(
    const float* __restrict__ x, const float* __restrict__ y,
    const float* __restrict__ gam, const float* __restrict__ bet,
    float* __restrict__ out, int doadd)
{
    __shared__ float sm[8];
    int row = blockIdx.x, tid = threadIdx.x;
    float v = x[row*DD + tid];
    if (doadd) v += y[row*DD + tid];

    float s = v;
    #pragma unroll
    for (int off=16; off; off>>=1) s += __shfl_xor_sync(0xffffffffu, s, off);
    if ((tid&31)==0) sm[tid>>5] = s;
    __syncthreads();
    if (tid < 32) {
        float r = (tid < 8) ? sm[tid] : 0.f;
        #pragma unroll
        for (int off=4; off; off>>=1) r += __shfl_xor_sync(0xffffffffu, r, off);
        if (tid==0) sm[0] = r;
    }
    __syncthreads();
    float mean = sm[0] * (1.f/DD);
    __syncthreads();

    float t = v - mean;
    float s2 = t*t;
    #pragma unroll
    for (int off=16; off; off>>=1) s2 += __shfl_xor_sync(0xffffffffu, s2, off);
    if ((tid&31)==0) sm[tid>>5] = s2;
    __syncthreads();
    if (tid < 32) {
        float r = (tid < 8) ? sm[tid] : 0.f;
        #pragma unroll
        for (int off=4; off; off>>=1) r += __shfl_xor_sync(0xffffffffu, r, off);
        if (tid==0) sm[0] = r;
    }
    __syncthreads();
    float var = sm[0] * (1.f/DD);
    out[row*DD + tid] = t * rsqrtf(var + 1e-5f) * gam[tid] + bet[tid];
}

// ---------------- launch ----------------
extern "C" void kernel_launch(void* const* d_in, const int* in_sizes, int n_in,
                              void* d_out, int out_size)
{
    const float* x_img          = (const float*)d_in[0];
    const void*  pmask          = (const void*)d_in[1];
    const int*   valid_idx      = (const int*)d_in[2];
    const float* pe_w           = (const float*)d_in[3];
    const float* pe_b           = (const float*)d_in[4];
    const float* spos           = (const float*)d_in[5];
    const float* Wqkv           = (const float*)d_in[6];
    const float* bqkv           = (const float*)d_in[7];
    const float* Wo             = (const float*)d_in[8];
    const float* bo             = (const float*)d_in[9];
    const float* ln1s           = (const float*)d_in[10];
    const float* ln1b           = (const float*)d_in[11];
    const float* W1             = (const float*)d_in[12];
    const float* b1             = (const float*)d_in[13];
    const float* W2             = (const float*)d_in[14];
    const float* b2             = (const float*)d_in[15];
    const float* ln2s           = (const float*)d_in[16];
    const float* ln2b           = (const float*)d_in[17];
    const float* nfs            = (const float*)d_in[18];
    const float* nfb            = (const float*)d_in[19];
    float* out = (float*)d_out;

    float *px, *pqkv, *patt, *py, *pff;
    cudaGetSymbolAddress((void**)&px,   g_x);
    cudaGetSymbolAddress((void**)&pqkv, g_qkv);
    cudaGetSymbolAddress((void**)&patt, g_att);
    cudaGetSymbolAddress((void**)&py,   g_y);
    cudaGetSymbolAddress((void**)&pff,  g_ff);

    build_vis_kernel<<<(BB*TT+255)/256, 256>>>(pmask, valid_idx);
    embed_kernel<<<MM/16, 256>>>(x_img, valid_idx, pe_w, pe_b, spos);

    for (int i = 0; i < NLAYERS; i++) {
        gemm_kernel<<<dim3(MM/128, 3*DD/128), 256>>>(px, Wqkv + i*3*DD*DD, bqkv + i*3*DD, pqkv, 3*DD, DD, 0);
        attn_kernel<<<dim3((LL+63)/64, BB*NHEAD), 256>>>(pqkv, patt);
        gemm_kernel<<<dim3(MM/128, DD/128), 256>>>(patt, Wo + i*DD*DD, bo + i*DD, py, DD, DD, 0);
        add_ln_kernel<<<MM, 256>>>(px, py, ln1s + i*DD, ln1b + i*DD, px, 1);
        gemm_kernel<<<dim3(MM/128, DFF/128), 256>>>(px, W1 + i*DFF*DD, b1 + i*DFF, pff, DFF, DD, 1);
        gemm_kernel<<<dim3(MM/128, DD/128), 256>>>(pff, W2 + i*DD*DFF, b2 + i*DD, py, DD, DFF, 0);
        add_ln_kernel<<<MM, 256>>>(px, py, ln2s + i*DD, ln2b + i*DD, px, 1);
    }
    add_ln_kernel<<<MM, 256>>>(px, px, nfs, nfb, out, 0);
}

// round 3
// speedup vs baseline: 1.0465x; 1.0465x over previous
#include <cuda_runtime.h>
#include <math.h>
#include <stdint.h>

#define BB 8
#define TT 90
#define HIMG 290
#define WIMG 180
#define PS 10
#define NWP 18
#define NP 522
#define PD 100
#define NV 94
#define KVIS 24
#define LL 2160
#define DD 256
#define NHEAD 8
#define DH 32
#define NLAYERS 6
#define DFF 1024
#define MM (BB*LL)   /* 17280 */

typedef unsigned long long ull;

// ---------------- f32x2 packed math helpers ----------------
__device__ __forceinline__ ull pack2(float lo, float hi) {
    ull d; asm("mov.b64 %0, {%1, %2};" : "=l"(d) : "f"(lo), "f"(hi)); return d;
}
__device__ __forceinline__ void unpack2(ull v, float& lo, float& hi) {
    asm("mov.b64 {%0, %1}, %2;" : "=f"(lo), "=f"(hi) : "l"(v));
}
__device__ __forceinline__ ull fma2(ull a, ull b, ull c) {
    ull d; asm("fma.rn.f32x2 %0, %1, %2, %3;" : "=l"(d) : "l"(a), "l"(b), "l"(c)); return d;
}
__device__ __forceinline__ ull mul2(ull a, ull b) {
    ull d; asm("mul.rn.f32x2 %0, %1, %2;" : "=l"(d) : "l"(a), "l"(b)); return d;
}

// ---------------- scratch (no cudaMalloc allowed) ----------------
__device__ float g_x[MM*DD];
__device__ float g_qkv[MM*3*DD];
__device__ float g_att[MM*DD];
__device__ float g_y[MM*DD];
__device__ float g_ff[MM*DFF];
__device__ int   g_tokv[MM];

// ---------------- token list: visible v per (b,t), in order ----------------
__global__ void build_vis_kernel(const void* __restrict__ mask_raw,
                                 const int* __restrict__ valid_idx)
{
    int bt = blockIdx.x*blockDim.x + threadIdx.x;
    if (bt >= BB*TT) return;

    const int*   mi = (const int*)mask_raw;
    const float* mf = (const float*)mask_raw;
    const unsigned char* mb = (const unsigned char*)mask_raw;

    int is_int = 1;
    for (int j = 0; j < NP; j++) {
        int w = mi[j];
        if (w != 0 && w != 1) { is_int = 0; break; }
    }
    int is_float = 0;
    if (!is_int) {
        is_float = 1;
        for (int j = 0; j < NP; j++) {
            float w = mf[j];
            if (w != 0.0f && w != 1.0f) { is_float = 0; break; }
        }
    }

    int base = bt*KVIS;
    int cnt = 0;
    for (int v = 0; v < NV; v++) {
        int idx = bt*NP + valid_idx[v];
        int masked;
        if (is_int)        masked = (mi[idx] != 0);
        else if (is_float) masked = (mf[idx] != 0.0f);
        else               masked = (mb[idx] != 0);
        if (!masked) {
            if (cnt < KVIS) g_tokv[base+cnt] = v;
            cnt++;
        }
    }
}

// ---------------- patchify + patch embed + pos encodings ----------------
__global__ void __launch_bounds__(256) embed_kernel(
    const float* __restrict__ img, const int* __restrict__ valid_idx,
    const float* __restrict__ Wpe, const float* __restrict__ bpe,
    const float* __restrict__ spos)
{
    __shared__ float pix[16][PD];
    __shared__ float wsm[DD][27];
    __shared__ int sm_v[16], sm_t[16], sm_off[16];
    int tid = threadIdx.x;
    int m0 = blockIdx.x * 16;
    if (tid < 16) {
        int m = m0 + tid;
        int b = m / LL;
        int l = m - b*LL;
        int t = l / KVIS;
        int v = g_tokv[m];
        int patch = valid_idx[v];
        int hp = patch / NWP, wp = patch - hp*NWP;
        sm_v[tid] = v; sm_t[tid] = t;
        sm_off[tid] = ((b*TT + t)*HIMG + hp*PS)*WIMG + wp*PS;
    }
    __syncthreads();
    for (int j = tid; j < 16*PD; j += 256) {
        int tok = j / PD, pd = j - tok*PD;
        int ph = pd / PS, pw = pd - ph*PS;
        pix[tok][pd] = img[sm_off[tok] + ph*WIMG + pw];
    }
    float acc[16];
    #pragma unroll
    for (int i = 0; i < 16; i++) acc[i] = 0.f;
    for (int k0 = 0; k0 < PD; k0 += 25) {
        __syncthreads();
        for (int j = tid; j < DD*25; j += 256) {
            int dd = j / 25, kk = j - dd*25;
            wsm[dd][kk] = Wpe[dd*PD + k0 + kk];
        }
        __syncthreads();
        #pragma unroll
        for (int kk = 0; kk < 25; kk++) {
            float w = wsm[tid][kk];
            #pragma unroll
            for (int tok = 0; tok < 16; tok++)
                acc[tok] = fmaf(w, pix[tok][k0+kk], acc[tok]);
        }
    }
    int d = tid;
    float freq = expf((float)(d & ~1) * (-9.210340371976184f / 256.f));
    float pb = bpe[d];
    #pragma unroll
    for (int tok = 0; tok < 16; tok++) {
        float val = (float)sm_t[tok] * freq;
        float pe = (d & 1) ? cosf(val) : sinf(val);
        g_x[(m0+tok)*DD + d] = acc[tok] + pb + spos[sm_v[tok]*DD + d] + pe;
    }
}

// ---------------- fp32 SGEMM with packed f32x2 FMA ----------------
// C[m,n] = sum_k A[m,k]*W[n,k] + bias[n]. BM=BN=128, BK=16, 256 thr, 8x8 tile.
__global__ void __launch_bounds__(256,2) gemm_kernel(
    const float* __restrict__ A, const float* __restrict__ W,
    const float* __restrict__ bias, float* __restrict__ C,
    int Ndim, int Kdim, int relu)
{
    __shared__ float As[16][132];
    __shared__ float Ws[16][132];
    int tid = threadIdx.x;
    int m0 = blockIdx.x * 128;
    int n0 = blockIdx.y * 128;
    int lr = tid >> 2;
    int lc = (tid & 3) << 2;
    const float* Ap = A + (m0 + lr)*Kdim + lc;
    const float* Wp = W + (n0 + lr)*Kdim + lc;
    int tx = tid & 15, ty = tid >> 4;
    ull acc2[8][4];
    #pragma unroll
    for (int i=0;i<8;i++)
        #pragma unroll
        for (int j=0;j<4;j++) acc2[i][j]=0ULL;

    for (int k0 = 0; k0 < Kdim; k0 += 16) {
        float4 a0 = *(const float4*)(Ap + k0);
        float4 a1 = *(const float4*)(Ap + 64*Kdim + k0);
        float4 w0 = *(const float4*)(Wp + k0);
        float4 w1 = *(const float4*)(Wp + 64*Kdim + k0);
        __syncthreads();
        As[lc+0][lr]=a0.x; As[lc+1][lr]=a0.y; As[lc+2][lr]=a0.z; As[lc+3][lr]=a0.w;
        As[lc+0][lr+64]=a1.x; As[lc+1][lr+64]=a1.y; As[lc+2][lr+64]=a1.z; As[lc+3][lr+64]=a1.w;
        Ws[lc+0][lr]=w0.x; Ws[lc+1][lr]=w0.y; Ws[lc+2][lr]=w0.z; Ws[lc+3][lr]=w0.w;
        Ws[lc+0][lr+64]=w1.x; Ws[lc+1][lr+64]=w1.y; Ws[lc+2][lr+64]=w1.z; Ws[lc+3][lr+64]=w1.w;
        __syncthreads();
        #pragma unroll
        for (int kk=0; kk<16; kk++) {
            float4 af0 = *(const float4*)(&As[kk][ty*8]);
            float4 af1 = *(const float4*)(&As[kk][ty*8+4]);
            ulonglong2 wv0 = *(const ulonglong2*)(&Ws[kk][tx*8]);
            ulonglong2 wv1 = *(const ulonglong2*)(&Ws[kk][tx*8+4]);
            ull wp2[4] = {wv0.x, wv0.y, wv1.x, wv1.y};
            float av[8] = {af0.x,af0.y,af0.z,af0.w,af1.x,af1.y,af1.z,af1.w};
            #pragma unroll
            for (int i=0;i<8;i++) {
                ull ai = pack2(av[i], av[i]);
                #pragma unroll
                for (int jp=0;jp<4;jp++)
                    acc2[i][jp] = fma2(ai, wp2[jp], acc2[i][jp]);
            }
        }
    }
    float bn[8];
    #pragma unroll
    for (int j=0;j<8;j++) bn[j] = bias[n0 + tx*8 + j];
    #pragma unroll
    for (int i=0;i<8;i++) {
        float vv[8];
        #pragma unroll
        for (int jp=0;jp<4;jp++) unpack2(acc2[i][jp], vv[2*jp], vv[2*jp+1]);
        #pragma unroll
        for (int j=0;j<8;j++) {
            float t = vv[j] + bn[j];
            if (relu) t = fmaxf(t, 0.f);
            vv[j] = t;
        }
        float* Cp = C + (m0 + ty*8 + i)*Ndim + n0 + tx*8;
        *(float4*)(Cp)   = make_float4(vv[0],vv[1],vv[2],vv[3]);
        *(float4*)(Cp+4) = make_float4(vv[4],vv[5],vv[6],vv[7]);
    }
}

// ---------------- flash attention, fp32 with f32x2 FMA ----------------
// BQ=BK=128, 256 threads. QK: 8x8 frags from transposed Qt/Kt. PV: 4x4 frags
// reading row-major P vectorized along k, V as ulonglong2 pairs.
#define NKT 17
#define QT_STRIDE 132
#define VS_STRIDE 36
#define PS_STRIDE 132
#define SMEM_ATTN ((2*32*QT_STRIDE + 128*VS_STRIDE + 128*PS_STRIDE + 3*128)*4)

__global__ void __launch_bounds__(256,1) attn_kernel(const float* __restrict__ qkv,
                                                     float* __restrict__ out)
{
    extern __shared__ float sm[];
    float* Qt    = sm;                         // [32][132]
    float* Kt    = Qt + 32*QT_STRIDE;          // [32][132]
    float* Vs    = Kt + 32*QT_STRIDE;          // [128][36]
    float* Psm   = Vs + 128*VS_STRIDE;         // [128][132]
    float* m_s   = Psm + 128*PS_STRIDE;        // [128]
    float* l_s   = m_s + 128;
    float* fac_s = l_s + 128;

    int tid = threadIdx.x;
    int q0 = blockIdx.x * 128;
    int b = blockIdx.y >> 3;
    int h = blockIdx.y & 7;
    const float* base = qkv + (size_t)b*LL*3*DD + h*DH;

    if (tid < 128) { m_s[tid] = -1e30f; l_s[tid] = 0.f; }

    // load Q tile transposed: Qt[d][r]
    #pragma unroll
    for (int it = 0; it < 4; it++) {
        int idx = it*256 + tid;
        int r = idx >> 3, d0 = (idx & 7)*4;
        int qrow = q0 + r;
        float4 q = (qrow < LL) ? *(const float4*)(base + (size_t)qrow*3*DD + d0)
                               : make_float4(0.f,0.f,0.f,0.f);
        Qt[(d0+0)*QT_STRIDE + r] = q.x;
        Qt[(d0+1)*QT_STRIDE + r] = q.y;
        Qt[(d0+2)*QT_STRIDE + r] = q.z;
        Qt[(d0+3)*QT_STRIDE + r] = q.w;
    }

    int tx = tid & 15, ty = tid >> 4;
    int R = ty*8, C = tx*8;
    int u = tid & 7, w = tid >> 3;

    ull o2[4][2];
    #pragma unroll
    for (int i=0;i<4;i++){ o2[i][0]=0ULL; o2[i][1]=0ULL; }
    const float scale = 0.17677669529663687f;  // 1/sqrt(32)

    for (int kt = 0; kt < NKT; kt++) {
        int k0t = kt*128;
        __syncthreads();   // prev PV done (also covers init/Q-load on kt=0)
        // load K transposed + V row-major
        #pragma unroll
        for (int it = 0; it < 4; it++) {
            int idx = it*256 + tid;
            int r = idx >> 3, d0 = (idx & 7)*4;
            int krow = k0t + r;
            float4 kq, vq;
            if (krow < LL) {
                kq = *(const float4*)(base + (size_t)krow*3*DD + DD   + d0);
                vq = *(const float4*)(base + (size_t)krow*3*DD + 2*DD + d0);
            } else {
                kq = make_float4(0.f,0.f,0.f,0.f);
                vq = kq;
            }
            Kt[(d0+0)*QT_STRIDE + r] = kq.x;
            Kt[(d0+1)*QT_STRIDE + r] = kq.y;
            Kt[(d0+2)*QT_STRIDE + r] = kq.z;
            Kt[(d0+3)*QT_STRIDE + r] = kq.w;
            *(float4*)(&Vs[r*VS_STRIDE + d0]) = vq;
        }
        __syncthreads();

        // ---- S = Q K^T (8x8 frag, f32x2 paired along cols) ----
        ull s2[8][4];
        #pragma unroll
        for (int i=0;i<8;i++)
            #pragma unroll
            for (int jp=0;jp<4;jp++) s2[i][jp]=0ULL;
        #pragma unroll 4
        for (int kk=0; kk<32; kk++) {
            const float* qr = &Qt[kk*QT_STRIDE + R];
            float4 a0 = *(const float4*)qr;
            float4 a1 = *(const float4*)(qr+4);
            const ulonglong2* kp = (const ulonglong2*)(&Kt[kk*QT_STRIDE + C]);
            ulonglong2 wv0 = kp[0], wv1 = kp[1];
            ull wp2[4] = {wv0.x, wv0.y, wv1.x, wv1.y};
            float av[8] = {a0.x,a0.y,a0.z,a0.w,a1.x,a1.y,a1.z,a1.w};
            #pragma unroll
            for (int i=0;i<8;i++) {
                ull ai = pack2(av[i], av[i]);
                #pragma unroll
                for (int jp=0;jp<4;jp++)
                    s2[i][jp] = fma2(ai, wp2[jp], s2[i][jp]);
            }
        }

        // ---- online softmax per row ----
        int tail = (k0t + 128 > LL);
        #pragma unroll
        for (int i=0;i<8;i++) {
            int row = R + i;
            float s[8];
            #pragma unroll
            for (int jp=0;jp<4;jp++) unpack2(s2[i][jp], s[2*jp], s[2*jp+1]);
            #pragma unroll
            for (int j=0;j<8;j++) s[j] *= scale;
            if (tail) {
                #pragma unroll
                for (int j=0;j<8;j++)
                    if (k0t + C + j >= LL) s[j] = -1e30f;
            }
            float rmax = s[0];
            #pragma unroll
            for (int j=1;j<8;j++) rmax = fmaxf(rmax, s[j]);
            rmax = fmaxf(rmax, __shfl_xor_sync(0xffffffffu, rmax, 1));
            rmax = fmaxf(rmax, __shfl_xor_sync(0xffffffffu, rmax, 2));
            rmax = fmaxf(rmax, __shfl_xor_sync(0xffffffffu, rmax, 4));
            rmax = fmaxf(rmax, __shfl_xor_sync(0xffffffffu, rmax, 8));
            float mold = m_s[row];
            float mnew = fmaxf(mold, rmax);
            float fac = __expf(mold - mnew);
            float ps = 0.f;
            #pragma unroll
            for (int j=0;j<8;j++) { s[j] = __expf(s[j] - mnew); ps += s[j]; }
            ps += __shfl_xor_sync(0xffffffffu, ps, 1);
            ps += __shfl_xor_sync(0xffffffffu, ps, 2);
            ps += __shfl_xor_sync(0xffffffffu, ps, 4);
            ps += __shfl_xor_sync(0xffffffffu, ps, 8);
            if (tx == 0) {
                m_s[row] = mnew;
                l_s[row] = l_s[row]*fac + ps;
                fac_s[row] = fac;
            }
            *(float4*)(&Psm[row*PS_STRIDE + C])   = make_float4(s[0],s[1],s[2],s[3]);
            *(float4*)(&Psm[row*PS_STRIDE + C+4]) = make_float4(s[4],s[5],s[6],s[7]);
        }
        __syncthreads();

        // ---- rescale O then O += P V (4x4 frag, f32x2 paired along cols) ----
        #pragma unroll
        for (int i=0;i<4;i++) {
            float f = fac_s[4*w + i];
            ull f2 = pack2(f, f);
            o2[i][0] = mul2(o2[i][0], f2);
            o2[i][1] = mul2(o2[i][1], f2);
        }
        #pragma unroll 2
        for (int kk0 = 0; kk0 < 128; kk0 += 4) {
            float4 p4[4];
            #pragma unroll
            for (int i=0;i<4;i++)
                p4[i] = *(const float4*)(&Psm[(4*w+i)*PS_STRIDE + kk0]);
            #pragma unroll
            for (int kk=0; kk<4; kk++) {
                ulonglong2 vv = *(const ulonglong2*)(&Vs[(kk0+kk)*VS_STRIDE + 4*u]);
                #pragma unroll
                for (int i=0;i<4;i++) {
                    float pk = (kk==0) ? p4[i].x : (kk==1) ? p4[i].y : (kk==2) ? p4[i].z : p4[i].w;
                    ull p2 = pack2(pk, pk);
                    o2[i][0] = fma2(p2, vv.x, o2[i][0]);
                    o2[i][1] = fma2(p2, vv.y, o2[i][1]);
                }
            }
        }
    }

    // ---- normalize + store ----
    #pragma unroll
    for (int i=0;i<4;i++) {
        int row = 4*w + i;
        int qrow = q0 + row;
        if (qrow < LL) {
            float linv = 1.f / l_s[row];
            float r0,r1,r2,r3;
            unpack2(o2[i][0], r0, r1);
            unpack2(o2[i][1], r2, r3);
            *(float4*)(out + ((size_t)b*LL + qrow)*DD + h*DH + 4*u)
                = make_float4(r0*linv, r1*linv, r2*linv, r3*linv);
        }
    }
}

// ---------------- residual add + LayerNorm (two-pass, exact) ----------------
__global__ void __launch_bounds__(256) add_ln_kernel(
    const float* __restrict__ x, const float* __restrict__ y,
    const float* __restrict__ gam, const float* __restrict__ bet,
    float* __restrict__ out, int doadd)
{
    __shared__ float sm[8];
    int row = blockIdx.x, tid = threadIdx.x;
    float v = x[row*DD + tid];
    if (doadd) v += y[row*DD + tid];

    float s = v;
    #pragma unroll
    for (int off=16; off; off>>=1) s += __shfl_xor_sync(0xffffffffu, s, off);
    if ((tid&31)==0) sm[tid>>5] = s;
    __syncthreads();
    if (tid < 32) {
        float r = (tid < 8) ? sm[tid] : 0.f;
        #pragma unroll
        for (int off=4; off; off>>=1) r += __shfl_xor_sync(0xffffffffu, r, off);
        if (tid==0) sm[0] = r;
    }
    __syncthreads();
    float mean = sm[0] * (1.f/DD);
    __syncthreads();

    float t = v - mean;
    float s2 = t*t;
    #pragma unroll
    for (int off=16; off; off>>=1) s2 += __shfl_xor_sync(0xffffffffu, s2, off);
    if ((tid&31)==0) sm[tid>>5] = s2;
    __syncthreads();
    if (tid < 32) {
        float r = (tid < 8) ? sm[tid] : 0.f;
        #pragma unroll
        for (int off=4; off; off>>=1) r += __shfl_xor_sync(0xffffffffu, r, off);
        if (tid==0) sm[0] = r;
    }
    __syncthreads();
    float var = sm[0] * (1.f/DD);
    out[row*DD + tid] = t * rsqrtf(var + 1e-5f) * gam[tid] + bet[tid];
}

// ---------------- launch ----------------
extern "C" void kernel_launch(void* const* d_in, const int* in_sizes, int n_in,
                              void* d_out, int out_size)
{
    const float* x_img          = (const float*)d_in[0];
    const void*  pmask          = (const void*)d_in[1];
    const int*   valid_idx      = (const int*)d_in[2];
    const float* pe_w           = (const float*)d_in[3];
    const float* pe_b           = (const float*)d_in[4];
    const float* spos           = (const float*)d_in[5];
    const float* Wqkv           = (const float*)d_in[6];
    const float* bqkv           = (const float*)d_in[7];
    const float* Wo             = (const float*)d_in[8];
    const float* bo             = (const float*)d_in[9];
    const float* ln1s           = (const float*)d_in[10];
    const float* ln1b           = (const float*)d_in[11];
    const float* W1             = (const float*)d_in[12];
    const float* b1             = (const float*)d_in[13];
    const float* W2             = (const float*)d_in[14];
    const float* b2             = (const float*)d_in[15];
    const float* ln2s           = (const float*)d_in[16];
    const float* ln2b           = (const float*)d_in[17];
    const float* nfs            = (const float*)d_in[18];
    const float* nfb            = (const float*)d_in[19];
    float* out = (float*)d_out;

    float *px, *pqkv, *patt, *py, *pff;
    cudaGetSymbolAddress((void**)&px,   g_x);
    cudaGetSymbolAddress((void**)&pqkv, g_qkv);
    cudaGetSymbolAddress((void**)&patt, g_att);
    cudaGetSymbolAddress((void**)&py,   g_y);
    cudaGetSymbolAddress((void**)&pff,  g_ff);

    static int smem_set = 0;
    if (!smem_set) {
        cudaFuncSetAttribute(attn_kernel, cudaFuncAttributeMaxDynamicSharedMemorySize, SMEM_ATTN);
        smem_set = 1;
    }

    build_vis_kernel<<<(BB*TT+255)/256, 256>>>(pmask, valid_idx);
    embed_kernel<<<MM/16, 256>>>(x_img, valid_idx, pe_w, pe_b, spos);

    for (int i = 0; i < NLAYERS; i++) {
        gemm_kernel<<<dim3(MM/128, 3*DD/128), 256>>>(px, Wqkv + i*3*DD*DD, bqkv + i*3*DD, pqkv, 3*DD, DD, 0);
        attn_kernel<<<dim3(NKT, BB*NHEAD), 256, SMEM_ATTN>>>(pqkv, patt);
        gemm_kernel<<<dim3(MM/128, DD/128), 256>>>(patt, Wo + i*DD*DD, bo + i*DD, py, DD, DD, 0);
        add_ln_kernel<<<MM, 256>>>(px, py, ln1s + i*DD, ln1b + i*DD, px, 1);
        gemm_kernel<<<dim3(MM/128, DFF/128), 256>>>(px, W1 + i*DFF*DD, b1 + i*DFF, pff, DFF, DD, 1);
        gemm_kernel<<<dim3(MM/128, DD/128), 256>>>(pff, W2 + i*DD*DFF, b2 + i*DD, py, DD, DFF, 0);
        add_ln_kernel<<<MM, 256>>>(px, py, ln2s + i*DD, ln2b + i*DD, px, 1);
    }
    add_ln_kernel<<<MM, 256>>>(px, px, nfs, nfb, out, 0);
}

// round 4
// speedup vs baseline: 1.1613x; 1.1096x over previous
#include <cuda_runtime.h>
#include <math.h>
#include <stdint.h>

#define BB 8
#define TT 90
#define HIMG 290
#define WIMG 180
#define PS 10
#define NWP 18
#define NP 522
#define PD 100
#define NV 94
#define KVIS 24
#define LL 2160
#define DD 256
#define NHEAD 8
#define DH 32
#define NLAYERS 6
#define DFF 1024
#define MM (BB*LL)   /* 17280 */

typedef unsigned long long ull;

// ---------------- f32x2 packed math helpers ----------------
__device__ __forceinline__ ull pack2(float lo, float hi) {
    ull d; asm("mov.b64 %0, {%1, %2};" : "=l"(d) : "f"(lo), "f"(hi)); return d;
}
__device__ __forceinline__ void unpack2(ull v, float& lo, float& hi) {
    asm("mov.b64 {%0, %1}, %2;" : "=f"(lo), "=f"(hi) : "l"(v));
}
__device__ __forceinline__ ull fma2(ull a, ull b, ull c) {
    ull d; asm("fma.rn.f32x2 %0, %1, %2, %3;" : "=l"(d) : "l"(a), "l"(b), "l"(c)); return d;
}
__device__ __forceinline__ ull mul2(ull a, ull b) {
    ull d; asm("mul.rn.f32x2 %0, %1, %2;" : "=l"(d) : "l"(a), "l"(b)); return d;
}

// ---------------- scratch (no cudaMalloc allowed) ----------------
__device__ float g_x[MM*DD];
__device__ float g_qkv[MM*3*DD];
__device__ float g_att[MM*DD];
__device__ float g_y[MM*DD];
__device__ float g_ff[MM*DFF];
__device__ int   g_tokv[MM];

// ---------------- token list: visible v per (b,t), in order ----------------
__global__ void build_vis_kernel(const void* __restrict__ mask_raw,
                                 const int* __restrict__ valid_idx)
{
    int bt = blockIdx.x*blockDim.x + threadIdx.x;
    if (bt >= BB*TT) return;

    const int*   mi = (const int*)mask_raw;
    const float* mf = (const float*)mask_raw;
    const unsigned char* mb = (const unsigned char*)mask_raw;

    int is_int = 1;
    for (int j = 0; j < NP; j++) {
        int w = mi[j];
        if (w != 0 && w != 1) { is_int = 0; break; }
    }
    int is_float = 0;
    if (!is_int) {
        is_float = 1;
        for (int j = 0; j < NP; j++) {
            float w = mf[j];
            if (w != 0.0f && w != 1.0f) { is_float = 0; break; }
        }
    }

    int base = bt*KVIS;
    int cnt = 0;
    for (int v = 0; v < NV; v++) {
        int idx = bt*NP + valid_idx[v];
        int masked;
        if (is_int)        masked = (mi[idx] != 0);
        else if (is_float) masked = (mf[idx] != 0.0f);
        else               masked = (mb[idx] != 0);
        if (!masked) {
            if (cnt < KVIS) g_tokv[base+cnt] = v;
            cnt++;
        }
    }
}

// ---------------- patchify + patch embed + pos encodings ----------------
__global__ void __launch_bounds__(256) embed_kernel(
    const float* __restrict__ img, const int* __restrict__ valid_idx,
    const float* __restrict__ Wpe, const float* __restrict__ bpe,
    const float* __restrict__ spos)
{
    __shared__ float pix[16][PD];
    __shared__ float wsm[DD][27];
    __shared__ int sm_v[16], sm_t[16], sm_off[16];
    int tid = threadIdx.x;
    int m0 = blockIdx.x * 16;
    if (tid < 16) {
        int m = m0 + tid;
        int b = m / LL;
        int l = m - b*LL;
        int t = l / KVIS;
        int v = g_tokv[m];
        int patch = valid_idx[v];
        int hp = patch / NWP, wp = patch - hp*NWP;
        sm_v[tid] = v; sm_t[tid] = t;
        sm_off[tid] = ((b*TT + t)*HIMG + hp*PS)*WIMG + wp*PS;
    }
    __syncthreads();
    for (int j = tid; j < 16*PD; j += 256) {
        int tok = j / PD, pd = j - tok*PD;
        int ph = pd / PS, pw = pd - ph*PS;
        pix[tok][pd] = img[sm_off[tok] + ph*WIMG + pw];
    }
    float acc[16];
    #pragma unroll
    for (int i = 0; i < 16; i++) acc[i] = 0.f;
    for (int k0 = 0; k0 < PD; k0 += 25) {
        __syncthreads();
        for (int j = tid; j < DD*25; j += 256) {
            int dd = j / 25, kk = j - dd*25;
            wsm[dd][kk] = Wpe[dd*PD + k0 + kk];
        }
        __syncthreads();
        #pragma unroll
        for (int kk = 0; kk < 25; kk++) {
            float w = wsm[tid][kk];
            #pragma unroll
            for (int tok = 0; tok < 16; tok++)
                acc[tok] = fmaf(w, pix[tok][k0+kk], acc[tok]);
        }
    }
    int d = tid;
    float freq = expf((float)(d & ~1) * (-9.210340371976184f / 256.f));
    float pb = bpe[d];
    #pragma unroll
    for (int tok = 0; tok < 16; tok++) {
        float val = (float)sm_t[tok] * freq;
        float pe = (d & 1) ? cosf(val) : sinf(val);
        g_x[(m0+tok)*DD + d] = acc[tok] + pb + spos[sm_v[tok]*DD + d] + pe;
    }
}

// ---------------- fp32 SGEMM, f32x2 FMA, double-buffered smem ----------------
// C[m,n] = sum_k A[m,k]*W[n,k] + bias[n]. BM=BN=128, BK=16, 256 thr, 8x8 tile.
__global__ void __launch_bounds__(256,2) gemm_kernel(
    const float* __restrict__ A, const float* __restrict__ W,
    const float* __restrict__ bias, float* __restrict__ C,
    int Ndim, int Kdim, int relu)
{
    __shared__ float As[2][16][132];
    __shared__ float Ws[2][16][132];
    int tid = threadIdx.x;
    int m0 = blockIdx.x * 128;
    int n0 = blockIdx.y * 128;
    int lr = tid >> 2;
    int lc = (tid & 3) << 2;
    const float* Ap = A + (m0 + lr)*Kdim + lc;
    const float* Wp = W + (n0 + lr)*Kdim + lc;
    int tx = tid & 15, ty = tid >> 4;
    ull acc2[8][4];
    #pragma unroll
    for (int i=0;i<8;i++)
        #pragma unroll
        for (int j=0;j<4;j++) acc2[i][j]=0ULL;

    // prologue: stage 0
    {
        float4 a0 = *(const float4*)(Ap);
        float4 a1 = *(const float4*)(Ap + 64*Kdim);
        float4 w0 = *(const float4*)(Wp);
        float4 w1 = *(const float4*)(Wp + 64*Kdim);
        As[0][lc+0][lr]=a0.x; As[0][lc+1][lr]=a0.y; As[0][lc+2][lr]=a0.z; As[0][lc+3][lr]=a0.w;
        As[0][lc+0][lr+64]=a1.x; As[0][lc+1][lr+64]=a1.y; As[0][lc+2][lr+64]=a1.z; As[0][lc+3][lr+64]=a1.w;
        Ws[0][lc+0][lr]=w0.x; Ws[0][lc+1][lr]=w0.y; Ws[0][lc+2][lr]=w0.z; Ws[0][lc+3][lr]=w0.w;
        Ws[0][lc+0][lr+64]=w1.x; Ws[0][lc+1][lr+64]=w1.y; Ws[0][lc+2][lr+64]=w1.z; Ws[0][lc+3][lr+64]=w1.w;
    }
    __syncthreads();

    int buf = 0;
    for (int k0 = 0; k0 < Kdim; k0 += 16) {
        int more = (k0 + 16 < Kdim);
        float4 na0, na1, nw0, nw1;
        if (more) {
            na0 = *(const float4*)(Ap + k0 + 16);
            na1 = *(const float4*)(Ap + 64*Kdim + k0 + 16);
            nw0 = *(const float4*)(Wp + k0 + 16);
            nw1 = *(const float4*)(Wp + 64*Kdim + k0 + 16);
        }
        #pragma unroll
        for (int kk=0; kk<16; kk++) {
            float4 af0 = *(const float4*)(&As[buf][kk][ty*8]);
            float4 af1 = *(const float4*)(&As[buf][kk][ty*8+4]);
            ulonglong2 wv0 = *(const ulonglong2*)(&Ws[buf][kk][tx*8]);
            ulonglong2 wv1 = *(const ulonglong2*)(&Ws[buf][kk][tx*8+4]);
            ull wp2[4] = {wv0.x, wv0.y, wv1.x, wv1.y};
            float av[8] = {af0.x,af0.y,af0.z,af0.w,af1.x,af1.y,af1.z,af1.w};
            #pragma unroll
            for (int i=0;i<8;i++) {
                ull ai = pack2(av[i], av[i]);
                #pragma unroll
                for (int jp=0;jp<4;jp++)
                    acc2[i][jp] = fma2(ai, wp2[jp], acc2[i][jp]);
            }
        }
        if (more) {
            int nb = buf ^ 1;
            As[nb][lc+0][lr]=na0.x; As[nb][lc+1][lr]=na0.y; As[nb][lc+2][lr]=na0.z; As[nb][lc+3][lr]=na0.w;
            As[nb][lc+0][lr+64]=na1.x; As[nb][lc+1][lr+64]=na1.y; As[nb][lc+2][lr+64]=na1.z; As[nb][lc+3][lr+64]=na1.w;
            Ws[nb][lc+0][lr]=nw0.x; Ws[nb][lc+1][lr]=nw0.y; Ws[nb][lc+2][lr]=nw0.z; Ws[nb][lc+3][lr]=nw0.w;
            Ws[nb][lc+0][lr+64]=nw1.x; Ws[nb][lc+1][lr+64]=nw1.y; Ws[nb][lc+2][lr+64]=nw1.z; Ws[nb][lc+3][lr+64]=nw1.w;
            __syncthreads();
        }
        buf ^= 1;
    }

    float bn[8];
    #pragma unroll
    for (int j=0;j<8;j++) bn[j] = bias[n0 + tx*8 + j];
    #pragma unroll
    for (int i=0;i<8;i++) {
        float vv[8];
        #pragma unroll
        for (int jp=0;jp<4;jp++) unpack2(acc2[i][jp], vv[2*jp], vv[2*jp+1]);
        #pragma unroll
        for (int j=0;j<8;j++) {
            float t = vv[j] + bn[j];
            if (relu) t = fmaxf(t, 0.f);
            vv[j] = t;
        }
        float* Cp = C + (m0 + ty*8 + i)*Ndim + n0 + tx*8;
        *(float4*)(Cp)   = make_float4(vv[0],vv[1],vv[2],vv[3]);
        *(float4*)(Cp+4) = make_float4(vv[4],vv[5],vv[6],vv[7]);
    }
}

// ---------------- flash attention, fp32 f32x2, BQ=128 BK=64, 2 blocks/SM ----
#define NKT2 34
#define QT_STRIDE 132
#define KT_STRIDE 68
#define VS_STRIDE 36
#define PS_STRIDE 68
#define SMEM_ATTN ((32*QT_STRIDE + 32*KT_STRIDE + 64*VS_STRIDE + 128*PS_STRIDE + 3*128)*4)

__global__ void __launch_bounds__(256,2) attn_kernel(const float* __restrict__ qkv,
                                                     float* __restrict__ out)
{
    extern __shared__ float sm[];
    float* Qt    = sm;                         // [32][132] transposed Q
    float* Kt    = Qt + 32*QT_STRIDE;          // [32][68]  transposed K
    float* Vs    = Kt + 32*KT_STRIDE;          // [64][36]  row-major V
    float* Psm   = Vs + 64*VS_STRIDE;          // [128][68] row-major P
    float* m_s   = Psm + 128*PS_STRIDE;        // [128]
    float* l_s   = m_s + 128;
    float* fac_s = l_s + 128;

    int tid = threadIdx.x;
    int q0 = blockIdx.x * 128;
    int b = blockIdx.y >> 3;
    int h = blockIdx.y & 7;
    const float* base = qkv + (size_t)b*LL*3*DD + h*DH;

    if (tid < 128) { m_s[tid] = -1e30f; l_s[tid] = 0.f; fac_s[tid] = 1.f; }

    // load Q tile transposed: Qt[d][r]
    #pragma unroll
    for (int it = 0; it < 4; it++) {
        int idx = it*256 + tid;
        int r = idx >> 3, d0 = (idx & 7)*4;
        int qrow = q0 + r;
        float4 q = (qrow < LL) ? *(const float4*)(base + (size_t)qrow*3*DD + d0)
                               : make_float4(0.f,0.f,0.f,0.f);
        Qt[(d0+0)*QT_STRIDE + r] = q.x;
        Qt[(d0+1)*QT_STRIDE + r] = q.y;
        Qt[(d0+2)*QT_STRIDE + r] = q.z;
        Qt[(d0+3)*QT_STRIDE + r] = q.w;
    }

    int tx = tid & 15, ty = tid >> 4;
    int R = ty*8, C = tx*4;
    int u = tid & 7, w = tid >> 3;

    ull o2[4][2];
    #pragma unroll
    for (int i=0;i<4;i++){ o2[i][0]=0ULL; o2[i][1]=0ULL; }
    const float scale = 0.17677669529663687f;  // 1/sqrt(32)

    for (int kt = 0; kt < NKT2; kt++) {
        int k0t = kt*64;
        __syncthreads();   // prev PV done (also covers init/Q-load on kt=0)
        // load K transposed + V row-major (64 rows)
        #pragma unroll
        for (int it = 0; it < 2; it++) {
            int idx = it*256 + tid;
            int r = idx >> 3, d0 = (idx & 7)*4;
            int krow = k0t + r;
            float4 kq, vq;
            if (krow < LL) {
                kq = *(const float4*)(base + (size_t)krow*3*DD + DD   + d0);
                vq = *(const float4*)(base + (size_t)krow*3*DD + 2*DD + d0);
            } else {
                kq = make_float4(0.f,0.f,0.f,0.f);
                vq = kq;
            }
            Kt[(d0+0)*KT_STRIDE + r] = kq.x;
            Kt[(d0+1)*KT_STRIDE + r] = kq.y;
            Kt[(d0+2)*KT_STRIDE + r] = kq.z;
            Kt[(d0+3)*KT_STRIDE + r] = kq.w;
            *(float4*)(&Vs[r*VS_STRIDE + d0]) = vq;
        }
        __syncthreads();

        // ---- S = Q K^T : rows R..R+7 (paired), cols C..C+3 ----
        ull s2[4][4];
        #pragma unroll
        for (int ip=0;ip<4;ip++)
            #pragma unroll
            for (int j=0;j<4;j++) s2[ip][j]=0ULL;
        #pragma unroll 4
        for (int kk=0; kk<32; kk++) {
            const float* qr = &Qt[kk*QT_STRIDE + R];
            ulonglong2 qv0 = *(const ulonglong2*)qr;        // rows (R,R+1),(R+2,R+3)
            ulonglong2 qv1 = *(const ulonglong2*)(qr+4);    // rows (R+4,R+5),(R+6,R+7)
            ull qp[4] = {qv0.x, qv0.y, qv1.x, qv1.y};
            float4 kf = *(const float4*)(&Kt[kk*KT_STRIDE + C]);
            ull kp[4] = {pack2(kf.x,kf.x), pack2(kf.y,kf.y),
                         pack2(kf.z,kf.z), pack2(kf.w,kf.w)};
            #pragma unroll
            for (int ip=0;ip<4;ip++)
                #pragma unroll
                for (int j=0;j<4;j++)
                    s2[ip][j] = fma2(qp[ip], kp[j], s2[ip][j]);
        }

        // ---- online softmax: each thread handles 8 rows (2 per pair) ----
        int tail = (k0t + 64 > LL);
        #pragma unroll
        for (int ip=0;ip<4;ip++) {
            float sa[4], sb[4];
            #pragma unroll
            for (int j=0;j<4;j++) unpack2(s2[ip][j], sa[j], sb[j]);
            #pragma unroll
            for (int half=0; half<2; half++) {
                float* s = half ? sb : sa;
                int row = R + 2*ip + half;
                #pragma unroll
                for (int j=0;j<4;j++) s[j] *= scale;
                if (tail) {
                    #pragma unroll
                    for (int j=0;j<4;j++)
                        if (k0t + C + j >= LL) s[j] = -1e30f;
                }
                float rmax = fmaxf(fmaxf(s[0],s[1]), fmaxf(s[2],s[3]));
                rmax = fmaxf(rmax, __shfl_xor_sync(0xffffffffu, rmax, 1));
                rmax = fmaxf(rmax, __shfl_xor_sync(0xffffffffu, rmax, 2));
                rmax = fmaxf(rmax, __shfl_xor_sync(0xffffffffu, rmax, 4));
                rmax = fmaxf(rmax, __shfl_xor_sync(0xffffffffu, rmax, 8));
                float mold = m_s[row];
                float mnew = fmaxf(mold, rmax);
                float fac = __expf(mold - mnew);
                float ps = 0.f;
                #pragma unroll
                for (int j=0;j<4;j++) { s[j] = __expf(s[j] - mnew); ps += s[j]; }
                ps += __shfl_xor_sync(0xffffffffu, ps, 1);
                ps += __shfl_xor_sync(0xffffffffu, ps, 2);
                ps += __shfl_xor_sync(0xffffffffu, ps, 4);
                ps += __shfl_xor_sync(0xffffffffu, ps, 8);
                if (tx == 0) {
                    m_s[row] = mnew;
                    l_s[row] = l_s[row]*fac + ps;
                    fac_s[row] = fac;
                }
                *(float4*)(&Psm[row*PS_STRIDE + C]) = make_float4(s[0],s[1],s[2],s[3]);
            }
        }
        __syncthreads();

        // ---- rescale O, then O += P V (rows 4w..4w+3, cols 4u..4u+3) ----
        #pragma unroll
        for (int i=0;i<4;i++) {
            float f = fac_s[4*w + i];
            ull f2 = pack2(f, f);
            o2[i][0] = mul2(o2[i][0], f2);
            o2[i][1] = mul2(o2[i][1], f2);
        }
        #pragma unroll 2
        for (int kk0 = 0; kk0 < 64; kk0 += 4) {
            float4 p4[4];
            #pragma unroll
            for (int i=0;i<4;i++)
                p4[i] = *(const float4*)(&Psm[(4*w+i)*PS_STRIDE + kk0]);
            #pragma unroll
            for (int kk=0; kk<4; kk++) {
                ulonglong2 vv = *(const ulonglong2*)(&Vs[(kk0+kk)*VS_STRIDE + 4*u]);
                #pragma unroll
                for (int i=0;i<4;i++) {
                    float pk = (kk==0) ? p4[i].x : (kk==1) ? p4[i].y : (kk==2) ? p4[i].z : p4[i].w;
                    ull p2 = pack2(pk, pk);
                    o2[i][0] = fma2(p2, vv.x, o2[i][0]);
                    o2[i][1] = fma2(p2, vv.y, o2[i][1]);
                }
            }
        }
    }

    // ---- normalize + store ----
    #pragma unroll
    for (int i=0;i<4;i++) {
        int row = 4*w + i;
        int qrow = q0 + row;
        if (qrow < LL) {
            float linv = 1.f / l_s[row];
            float r0,r1,r2,r3;
            unpack2(o2[i][0], r0, r1);
            unpack2(o2[i][1], r2, r3);
            *(float4*)(out + ((size_t)b*LL + qrow)*DD + h*DH + 4*u)
                = make_float4(r0*linv, r1*linv, r2*linv, r3*linv);
        }
    }
}

// ---------------- residual add + LayerNorm (warp per row, shuffle-only) -----
__global__ void __launch_bounds__(256) add_ln_kernel(
    const float* __restrict__ x, const float* __restrict__ y,
    const float* __restrict__ gam, const float* __restrict__ bet,
    float* __restrict__ out, int doadd)
{
    int warp = threadIdx.x >> 5, lane = threadIdx.x & 31;
    int row = blockIdx.x*8 + warp;
    const float* xr = x + (size_t)row*DD + lane*8;
    float v[8];
    float4 va = *(const float4*)(xr);
    float4 vb = *(const float4*)(xr + 4);
    v[0]=va.x; v[1]=va.y; v[2]=va.z; v[3]=va.w;
    v[4]=vb.x; v[5]=vb.y; v[6]=vb.z; v[7]=vb.w;
    if (doadd) {
        const float* yr = y + (size_t)row*DD + lane*8;
        float4 ya = *(const float4*)(yr);
        float4 yb = *(const float4*)(yr + 4);
        v[0]+=ya.x; v[1]+=ya.y; v[2]+=ya.z; v[3]+=ya.w;
        v[4]+=yb.x; v[5]+=yb.y; v[6]+=yb.z; v[7]+=yb.w;
    }
    float s = 0.f;
    #pragma unroll
    for (int i=0;i<8;i++) s += v[i];
    #pragma unroll
    for (int off=16; off; off>>=1) s += __shfl_xor_sync(0xffffffffu, s, off);
    float mean = s * (1.f/DD);
    float s2 = 0.f;
    #pragma unroll
    for (int i=0;i<8;i++) { v[i] -= mean; s2 += v[i]*v[i]; }
    #pragma unroll
    for (int off=16; off; off>>=1) s2 += __shfl_xor_sync(0xffffffffu, s2, off);
    float rstd = rsqrtf(s2 * (1.f/DD) + 1e-5f);
    const float* gp = gam + lane*8;
    const float* bp = bet + lane*8;
    float4 ga = *(const float4*)(gp);
    float4 gb = *(const float4*)(gp+4);
    float4 ba = *(const float4*)(bp);
    float4 bb = *(const float4*)(bp+4);
    float g[8] = {ga.x,ga.y,ga.z,ga.w,gb.x,gb.y,gb.z,gb.w};
    float be[8] = {ba.x,ba.y,ba.z,ba.w,bb.x,bb.y,bb.z,bb.w};
    float o[8];
    #pragma unroll
    for (int i=0;i<8;i++) o[i] = v[i]*rstd*g[i] + be[i];
    float* op = out + (size_t)row*DD + lane*8;
    *(float4*)(op)   = make_float4(o[0],o[1],o[2],o[3]);
    *(float4*)(op+4) = make_float4(o[4],o[5],o[6],o[7]);
}

// ---------------- launch ----------------
extern "C" void kernel_launch(void* const* d_in, const int* in_sizes, int n_in,
                              void* d_out, int out_size)
{
    const float* x_img          = (const float*)d_in[0];
    const void*  pmask          = (const void*)d_in[1];
    const int*   valid_idx      = (const int*)d_in[2];
    const float* pe_w           = (const float*)d_in[3];
    const float* pe_b           = (const float*)d_in[4];
    const float* spos           = (const float*)d_in[5];
    const float* Wqkv           = (const float*)d_in[6];
    const float* bqkv           = (const float*)d_in[7];
    const float* Wo             = (const float*)d_in[8];
    const float* bo             = (const float*)d_in[9];
    const float* ln1s           = (const float*)d_in[10];
    const float* ln1b           = (const float*)d_in[11];
    const float* W1             = (const float*)d_in[12];
    const float* b1             = (const float*)d_in[13];
    const float* W2             = (const float*)d_in[14];
    const float* b2             = (const float*)d_in[15];
    const float* ln2s           = (const float*)d_in[16];
    const float* ln2b           = (const float*)d_in[17];
    const float* nfs            = (const float*)d_in[18];
    const float* nfb            = (const float*)d_in[19];
    float* out = (float*)d_out;

    float *px, *pqkv, *patt, *py, *pff;
    cudaGetSymbolAddress((void**)&px,   g_x);
    cudaGetSymbolAddress((void**)&pqkv, g_qkv);
    cudaGetSymbolAddress((void**)&patt, g_att);
    cudaGetSymbolAddress((void**)&py,   g_y);
    cudaGetSymbolAddress((void**)&pff,  g_ff);

    cudaFuncSetAttribute(attn_kernel, cudaFuncAttributeMaxDynamicSharedMemorySize, SMEM_ATTN);

    build_vis_kernel<<<(BB*TT+255)/256, 256>>>(pmask, valid_idx);
    embed_kernel<<<MM/16, 256>>>(x_img, valid_idx, pe_w, pe_b, spos);

    for (int i = 0; i < NLAYERS; i++) {
        gemm_kernel<<<dim3(MM/128, 3*DD/128), 256>>>(px, Wqkv + i*3*DD*DD, bqkv + i*3*DD, pqkv, 3*DD, DD, 0);
        attn_kernel<<<dim3((LL+127)/128, BB*NHEAD), 256, SMEM_ATTN>>>(pqkv, patt);
        gemm_kernel<<<dim3(MM/128, DD/128), 256>>>(patt, Wo + i*DD*DD, bo + i*DD, py, DD, DD, 0);
        add_ln_kernel<<<MM/8, 256>>>(px, py, ln1s + i*DD, ln1b + i*DD, px, 1);
        gemm_kernel<<<dim3(MM/128, DFF/128), 256>>>(px, W1 + i*DFF*DD, b1 + i*DFF, pff, DFF, DD, 1);
        gemm_kernel<<<dim3(MM/128, DD/128), 256>>>(pff, W2 + i*DD*DFF, b2 + i*DD, py, DD, DFF, 0);
        add_ln_kernel<<<MM/8, 256>>>(px, py, ln2s + i*DD, ln2b + i*DD, px, 1);
    }
    add_ln_kernel<<<MM/8, 256>>>(px, px, nfs, nfb, out, 0);
}

// round 5
// speedup vs baseline: 2.5611x; 2.2055x over previous
#include <cuda_runtime.h>
#include <cuda_bf16.h>
#include <math.h>
#include <stdint.h>

#define BB 8
#define TT 90
#define HIMG 290
#define WIMG 180
#define PS 10
#define NWP 18
#define NP 522
#define PD 100
#define NV 94
#define KVIS 24
#define LL 2160
#define DD 256
#define NHEAD 8
#define DH 32
#define NLAYERS 6
#define DFF 1024
#define MM (BB*LL)   /* 17280 */

// ---------------- scratch (no cudaMalloc allowed) ----------------
__device__ float g_x[MM*DD];
__device__ float g_qkv[MM*3*DD];
__device__ float g_att[MM*DD];
__device__ float g_y[MM*DD];
__device__ float g_ff[MM*DFF];
__device__ int   g_tokv[MM];

// ---------------- mma / ldmatrix / bf16-split helpers ----------------
__device__ __forceinline__ unsigned sptr(const void* p) {
    return (unsigned)__cvta_generic_to_shared(p);
}
__device__ __forceinline__ void ldsm4(unsigned &r0, unsigned &r1, unsigned &r2, unsigned &r3, unsigned addr) {
    asm volatile("ldmatrix.sync.aligned.m8n8.x4.shared.b16 {%0,%1,%2,%3}, [%4];"
                 : "=r"(r0), "=r"(r1), "=r"(r2), "=r"(r3) : "r"(addr));
}
__device__ __forceinline__ void mma_bf16(float* c, const unsigned* a, unsigned b0, unsigned b1) {
    asm volatile("mma.sync.aligned.m16n8k16.row.col.f32.bf16.bf16.f32 "
                 "{%0,%1,%2,%3}, {%4,%5,%6,%7}, {%8,%9}, {%0,%1,%2,%3};"
                 : "+f"(c[0]), "+f"(c[1]), "+f"(c[2]), "+f"(c[3])
                 : "r"(a[0]), "r"(a[1]), "r"(a[2]), "r"(a[3]), "r"(b0), "r"(b1));
}
// split two f32 into packed bf16 hi and lo words
__device__ __forceinline__ void split2(float x0, float x1, unsigned &h, unsigned &l) {
    __nv_bfloat16 h0 = __float2bfloat16(x0), h1 = __float2bfloat16(x1);
    float r0 = x0 - __bfloat162float(h0), r1 = x1 - __bfloat162float(h1);
    __nv_bfloat16 l0 = __float2bfloat16(r0), l1 = __float2bfloat16(r1);
    h = (unsigned)__bfloat16_as_ushort(h0) | ((unsigned)__bfloat16_as_ushort(h1) << 16);
    l = (unsigned)__bfloat16_as_ushort(l0) | ((unsigned)__bfloat16_as_ushort(l1) << 16);
}
// convert 8 f32 -> hi/lo bf16 rows (16B each), store to smem
__device__ __forceinline__ void cvt_store8(__nv_bfloat16* dstH, __nv_bfloat16* dstL,
                                           float4 v0, float4 v1) {
    unsigned h[4], l[4];
    split2(v0.x, v0.y, h[0], l[0]);
    split2(v0.z, v0.w, h[1], l[1]);
    split2(v1.x, v1.y, h[2], l[2]);
    split2(v1.z, v1.w, h[3], l[3]);
    *(uint4*)dstH = make_uint4(h[0], h[1], h[2], h[3]);
    *(uint4*)dstL = make_uint4(l[0], l[1], l[2], l[3]);
}

// ---------------- token list: visible v per (b,t), in order ----------------
__global__ void build_vis_kernel(const void* __restrict__ mask_raw,
                                 const int* __restrict__ valid_idx)
{
    int bt = blockIdx.x*blockDim.x + threadIdx.x;
    if (bt >= BB*TT) return;

    const int*   mi = (const int*)mask_raw;
    const float* mf = (const float*)mask_raw;
    const unsigned char* mb = (const unsigned char*)mask_raw;

    int is_int = 1;
    for (int j = 0; j < NP; j++) {
        int w = mi[j];
        if (w != 0 && w != 1) { is_int = 0; break; }
    }
    int is_float = 0;
    if (!is_int) {
        is_float = 1;
        for (int j = 0; j < NP; j++) {
            float w = mf[j];
            if (w != 0.0f && w != 1.0f) { is_float = 0; break; }
        }
    }

    int base = bt*KVIS;
    int cnt = 0;
    for (int v = 0; v < NV; v++) {
        int idx = bt*NP + valid_idx[v];
        int masked;
        if (is_int)        masked = (mi[idx] != 0);
        else if (is_float) masked = (mf[idx] != 0.0f);
        else               masked = (mb[idx] != 0);
        if (!masked) {
            if (cnt < KVIS) g_tokv[base+cnt] = v;
            cnt++;
        }
    }
}

// ---------------- patchify + patch embed + pos encodings ----------------
__global__ void __launch_bounds__(256) embed_kernel(
    const float* __restrict__ img, const int* __restrict__ valid_idx,
    const float* __restrict__ Wpe, const float* __restrict__ bpe,
    const float* __restrict__ spos)
{
    __shared__ float pix[16][PD];
    __shared__ float wsm[DD][27];
    __shared__ int sm_v[16], sm_t[16], sm_off[16];
    int tid = threadIdx.x;
    int m0 = blockIdx.x * 16;
    if (tid < 16) {
        int m = m0 + tid;
        int b = m / LL;
        int l = m - b*LL;
        int t = l / KVIS;
        int v = g_tokv[m];
        int patch = valid_idx[v];
        int hp = patch / NWP, wp = patch - hp*NWP;
        sm_v[tid] = v; sm_t[tid] = t;
        sm_off[tid] = ((b*TT + t)*HIMG + hp*PS)*WIMG + wp*PS;
    }
    __syncthreads();
    for (int j = tid; j < 16*PD; j += 256) {
        int tok = j / PD, pd = j - tok*PD;
        int ph = pd / PS, pw = pd - ph*PS;
        pix[tok][pd] = img[sm_off[tok] + ph*WIMG + pw];
    }
    float acc[16];
    #pragma unroll
    for (int i = 0; i < 16; i++) acc[i] = 0.f;
    for (int k0 = 0; k0 < PD; k0 += 25) {
        __syncthreads();
        for (int j = tid; j < DD*25; j += 256) {
            int dd = j / 25, kk = j - dd*25;
            wsm[dd][kk] = Wpe[dd*PD + k0 + kk];
        }
        __syncthreads();
        #pragma unroll
        for (int kk = 0; kk < 25; kk++) {
            float w = wsm[tid][kk];
            #pragma unroll
            for (int tok = 0; tok < 16; tok++)
                acc[tok] = fmaf(w, pix[tok][k0+kk], acc[tok]);
        }
    }
    int d = tid;
    float freq = expf((float)(d & ~1) * (-9.210340371976184f / 256.f));
    float pb = bpe[d];
    #pragma unroll
    for (int tok = 0; tok < 16; tok++) {
        float val = (float)sm_t[tok] * freq;
        float pe = (d & 1) ? cosf(val) : sinf(val);
        g_x[(m0+tok)*DD + d] = acc[tok] + pb + spos[sm_v[tok]*DD + d] + pe;
    }
}

// ---------------- bf16-split tensor-core GEMM ----------------
// C[m,n] = sum_k A[m,k]*W[n,k] + bias[n].  Block 128x128, BK=16, 256 thr.
// 8 warps in 4(m) x 2(n); warp tile 32x64: 2 m-atoms x 8 n-atoms of m16n8k16.
#define GSTR 24
#define GEMM_AS (128*GSTR)
#define GEMM_SMEM (2*4*GEMM_AS*2)

__global__ void __launch_bounds__(256,2) gemm_kernel(
    const float* __restrict__ A, const float* __restrict__ W,
    const float* __restrict__ bias, float* __restrict__ C,
    int Ndim, int Kdim, int relu)
{
    extern __shared__ __align__(16) char smraw[];
    __nv_bfloat16* smb = (__nv_bfloat16*)smraw;
    int tid = threadIdx.x, lane = tid & 31, wid = tid >> 5;
    int wm = wid >> 1, wn = wid & 1;
    int m0 = blockIdx.x*128, n0 = blockIdx.y*128;
    int lrow = tid >> 1, lk = (tid & 1) << 3;
    const float* Ap = A + (size_t)(m0 + lrow)*Kdim + lk;
    const float* Wp = W + (size_t)(n0 + lrow)*Kdim + lk;

    float acc[2][8][4];
    #pragma unroll
    for (int i=0;i<2;i++)
        #pragma unroll
        for (int j=0;j<8;j++)
            #pragma unroll
            for (int q=0;q<4;q++) acc[i][j][q]=0.f;

    // ldmatrix lane address components
    int arow = wm*32 + (lane & 15);
    int akoff = (lane >> 4) << 3;
    int brow = wn*64 + ((lane >> 4) << 3) + (lane & 7);
    int bkoff = ((lane >> 3) & 1) << 3;

    // prologue: stage 0
    {
        float4 fa0 = *(const float4*)(Ap);
        float4 fa1 = *(const float4*)(Ap + 4);
        float4 fw0 = *(const float4*)(Wp);
        float4 fw1 = *(const float4*)(Wp + 4);
        __nv_bfloat16* Ah = smb;
        cvt_store8(Ah + 0*GEMM_AS + lrow*GSTR + lk, Ah + 1*GEMM_AS + lrow*GSTR + lk, fa0, fa1);
        cvt_store8(Ah + 2*GEMM_AS + lrow*GSTR + lk, Ah + 3*GEMM_AS + lrow*GSTR + lk, fw0, fw1);
    }
    __syncthreads();

    int buf = 0;
    for (int k0 = 0; k0 < Kdim; k0 += 16) {
        int more = (k0 + 16 < Kdim);
        float4 fa0, fa1, fw0, fw1;
        if (more) {
            fa0 = *(const float4*)(Ap + k0 + 16);
            fa1 = *(const float4*)(Ap + k0 + 20);
            fw0 = *(const float4*)(Wp + k0 + 16);
            fw1 = *(const float4*)(Wp + k0 + 20);
        }
        __nv_bfloat16* Ah = smb + buf*4*GEMM_AS;
        __nv_bfloat16* Al = Ah + GEMM_AS;
        __nv_bfloat16* Wh = Al + GEMM_AS;
        __nv_bfloat16* Wl = Wh + GEMM_AS;

        unsigned ah0[4], al0[4], ah1[4], al1[4];
        ldsm4(ah0[0],ah0[1],ah0[2],ah0[3], sptr(Ah + arow*GSTR + akoff));
        ldsm4(al0[0],al0[1],al0[2],al0[3], sptr(Al + arow*GSTR + akoff));
        ldsm4(ah1[0],ah1[1],ah1[2],ah1[3], sptr(Ah + (arow+16)*GSTR + akoff));
        ldsm4(al1[0],al1[1],al1[2],al1[3], sptr(Al + (arow+16)*GSTR + akoff));

        #pragma unroll
        for (int p = 0; p < 4; p++) {
            unsigned bh[4], bl[4];
            ldsm4(bh[0],bh[1],bh[2],bh[3], sptr(Wh + (brow + p*16)*GSTR + bkoff));
            ldsm4(bl[0],bl[1],bl[2],bl[3], sptr(Wl + (brow + p*16)*GSTR + bkoff));
            mma_bf16(acc[0][2*p],   ah0, bh[0], bh[1]);
            mma_bf16(acc[0][2*p],   ah0, bl[0], bl[1]);
            mma_bf16(acc[0][2*p],   al0, bh[0], bh[1]);
            mma_bf16(acc[0][2*p+1], ah0, bh[2], bh[3]);
            mma_bf16(acc[0][2*p+1], ah0, bl[2], bl[3]);
            mma_bf16(acc[0][2*p+1], al0, bh[2], bh[3]);
            mma_bf16(acc[1][2*p],   ah1, bh[0], bh[1]);
            mma_bf16(acc[1][2*p],   ah1, bl[0], bl[1]);
            mma_bf16(acc[1][2*p],   al1, bh[0], bh[1]);
            mma_bf16(acc[1][2*p+1], ah1, bh[2], bh[3]);
            mma_bf16(acc[1][2*p+1], ah1, bl[2], bl[3]);
            mma_bf16(acc[1][2*p+1], al1, bh[2], bh[3]);
        }

        if (more) {
            __nv_bfloat16* nAh = smb + (buf^1)*4*GEMM_AS;
            cvt_store8(nAh + 0*GEMM_AS + lrow*GSTR + lk, nAh + 1*GEMM_AS + lrow*GSTR + lk, fa0, fa1);
            cvt_store8(nAh + 2*GEMM_AS + lrow*GSTR + lk, nAh + 3*GEMM_AS + lrow*GSTR + lk, fw0, fw1);
            __syncthreads();
        }
        buf ^= 1;
    }

    // epilogue
    int r0 = lane >> 2;
    int c2 = (lane & 3) << 1;
    #pragma unroll
    for (int ma = 0; ma < 2; ma++) {
        #pragma unroll
        for (int na = 0; na < 8; na++) {
            int col = n0 + wn*64 + na*8 + c2;
            float2 bsv = *(const float2*)(bias + col);
            float v0 = acc[ma][na][0] + bsv.x;
            float v1 = acc[ma][na][1] + bsv.y;
            float v2 = acc[ma][na][2] + bsv.x;
            float v3 = acc[ma][na][3] + bsv.y;
            if (relu) {
                v0 = fmaxf(v0,0.f); v1 = fmaxf(v1,0.f);
                v2 = fmaxf(v2,0.f); v3 = fmaxf(v3,0.f);
            }
            int row = m0 + wm*32 + ma*16 + r0;
            *(float2*)(C + (size_t)row*Ndim + col) = make_float2(v0, v1);
            *(float2*)(C + (size_t)(row+8)*Ndim + col) = make_float2(v2, v3);
        }
    }
}

// ---------------- flash attention, bf16-split tensor cores ----------------
// BQ=128 (8 warps x 16 q-rows), BK=64, DH=32. Softmax + P entirely in regs.
#define ATSTR 40
#define VSTR 72
#define ATT_SMEM ((2*128*ATSTR + 2*64*ATSTR + 2*32*VSTR)*2)

__global__ void __launch_bounds__(256,2) attn_kernel(const float* __restrict__ qkv,
                                                     float* __restrict__ out)
{
    extern __shared__ __align__(16) char smraw[];
    __nv_bfloat16* Qh = (__nv_bfloat16*)smraw;       // [128][ATSTR]
    __nv_bfloat16* Ql = Qh + 128*ATSTR;
    __nv_bfloat16* Kh = Ql + 128*ATSTR;              // [64][ATSTR]
    __nv_bfloat16* Kl = Kh + 64*ATSTR;
    __nv_bfloat16* Vh = Kl + 64*ATSTR;               // [32][VSTR] transposed
    __nv_bfloat16* Vl = Vh + 32*VSTR;

    int tid = threadIdx.x, lane = tid & 31, wid = tid >> 5;
    int q0 = blockIdx.x * 128;
    int b = blockIdx.y >> 3, h = blockIdx.y & 7;
    const float* base = qkv + (size_t)b*LL*3*DD + h*DH;

    // ---- load + convert Q tile ----
    {
        int row = tid >> 1, kh2 = (tid & 1) << 4;
        int qrow = q0 + row;
        float4 v0, v1, v2, v3;
        if (qrow < LL) {
            const float* p = base + (size_t)qrow*3*DD + kh2;
            v0 = *(const float4*)(p);
            v1 = *(const float4*)(p+4);
            v2 = *(const float4*)(p+8);
            v3 = *(const float4*)(p+12);
        } else {
            v0 = make_float4(0.f,0.f,0.f,0.f); v1=v0; v2=v0; v3=v0;
        }
        cvt_store8(Qh + row*ATSTR + kh2,     Ql + row*ATSTR + kh2,     v0, v1);
        cvt_store8(Qh + row*ATSTR + kh2 + 8, Ql + row*ATSTR + kh2 + 8, v2, v3);
    }

    int arow = wid*16 + (lane & 15);
    int akoff = (lane >> 4) << 3;
    int brow = ((lane >> 4) << 3) + (lane & 7);
    int bkoff = ((lane >> 3) & 1) << 3;
    int c2 = (lane & 3) << 1;

    float sO[4][4];
    #pragma unroll
    for (int i=0;i<4;i++)
        #pragma unroll
        for (int j=0;j<4;j++) sO[i][j]=0.f;
    float mrow[2] = {-1e30f, -1e30f};
    float lrow[2] = {0.f, 0.f};
    const float scale = 0.17677669529663687f;  // 1/sqrt(32)

    for (int kt = 0; kt < 34; kt++) {
        int k0t = kt*64;
        __syncthreads();   // previous tile's PV reads done (covers Q store on kt=0)
        // ---- load + convert K (row-major) and V (transposed) ----
        {
            int r = tid >> 2, d0 = (tid & 3) << 3;
            int krow = k0t + r;
            float4 k0, k1, w0, w1;
            if (krow < LL) {
                const float* pk = base + (size_t)krow*3*DD + DD + d0;
                const float* pv = base + (size_t)krow*3*DD + 2*DD + d0;
                k0 = *(const float4*)(pk); k1 = *(const float4*)(pk+4);
                w0 = *(const float4*)(pv); w1 = *(const float4*)(pv+4);
            } else {
                k0 = make_float4(0.f,0.f,0.f,0.f); k1=k0; w0=k0; w1=k0;
            }
            cvt_store8(Kh + r*ATSTR + d0, Kl + r*ATSTR + d0, k0, k1);
            float vv[8] = {w0.x,w0.y,w0.z,w0.w,w1.x,w1.y,w1.z,w1.w};
            #pragma unroll
            for (int j = 0; j < 8; j++) {
                __nv_bfloat16 hh = __float2bfloat16(vv[j]);
                Vh[(d0+j)*VSTR + r] = hh;
                Vl[(d0+j)*VSTR + r] = __float2bfloat16(vv[j] - __bfloat162float(hh));
            }
        }
        __syncthreads();

        // ---- S = Q K^T ----
        float s[8][4];
        #pragma unroll
        for (int i=0;i<8;i++)
            #pragma unroll
            for (int j=0;j<4;j++) s[i][j]=0.f;
        #pragma unroll
        for (int ks = 0; ks < 2; ks++) {
            unsigned ah[4], al[4];
            ldsm4(ah[0],ah[1],ah[2],ah[3], sptr(Qh + arow*ATSTR + ks*16 + akoff));
            ldsm4(al[0],al[1],al[2],al[3], sptr(Ql + arow*ATSTR + ks*16 + akoff));
            #pragma unroll
            for (int p = 0; p < 4; p++) {
                unsigned bh[4], bl[4];
                ldsm4(bh[0],bh[1],bh[2],bh[3], sptr(Kh + (brow + p*16)*ATSTR + ks*16 + bkoff));
                ldsm4(bl[0],bl[1],bl[2],bl[3], sptr(Kl + (brow + p*16)*ATSTR + ks*16 + bkoff));
                mma_bf16(s[2*p],   ah, bh[0], bh[1]);
                mma_bf16(s[2*p],   ah, bl[0], bl[1]);
                mma_bf16(s[2*p],   al, bh[0], bh[1]);
                mma_bf16(s[2*p+1], ah, bh[2], bh[3]);
                mma_bf16(s[2*p+1], ah, bl[2], bl[3]);
                mma_bf16(s[2*p+1], al, bh[2], bh[3]);
            }
        }

        // ---- online softmax (per lane: rows r0 and r0+8, 16 vals each) ----
        int tail = (k0t + 64 > LL);
        float fac[2];
        #pragma unroll
        for (int hf = 0; hf < 2; hf++) {
            float vmax = -1e30f;
            #pragma unroll
            for (int na = 0; na < 8; na++) {
                float v0 = s[na][2*hf]   * scale;
                float v1 = s[na][2*hf+1] * scale;
                if (tail) {
                    if (k0t + na*8 + c2     >= LL) v0 = -1e30f;
                    if (k0t + na*8 + c2 + 1 >= LL) v1 = -1e30f;
                }
                s[na][2*hf] = v0; s[na][2*hf+1] = v1;
                vmax = fmaxf(vmax, fmaxf(v0, v1));
            }
            vmax = fmaxf(vmax, __shfl_xor_sync(0xffffffffu, vmax, 1));
            vmax = fmaxf(vmax, __shfl_xor_sync(0xffffffffu, vmax, 2));
            float mnew = fmaxf(mrow[hf], vmax);
            fac[hf] = __expf(mrow[hf] - mnew);
            mrow[hf] = mnew;
            float ps = 0.f;
            #pragma unroll
            for (int na = 0; na < 8; na++) {
                float p0 = __expf(s[na][2*hf]   - mnew);
                float p1 = __expf(s[na][2*hf+1] - mnew);
                s[na][2*hf] = p0; s[na][2*hf+1] = p1;
                ps += p0 + p1;
            }
            ps += __shfl_xor_sync(0xffffffffu, ps, 1);
            ps += __shfl_xor_sync(0xffffffffu, ps, 2);
            lrow[hf] = lrow[hf]*fac[hf] + ps;
        }

        // ---- pack P into A-operand fragments (hi/lo) ----
        unsigned pah[4][4], pal[4][4];
        #pragma unroll
        for (int ks = 0; ks < 4; ks++) {
            split2(s[2*ks][0],   s[2*ks][1],   pah[ks][0], pal[ks][0]);
            split2(s[2*ks][2],   s[2*ks][3],   pah[ks][1], pal[ks][1]);
            split2(s[2*ks+1][0], s[2*ks+1][1], pah[ks][2], pal[ks][2]);
            split2(s[2*ks+1][2], s[2*ks+1][3], pah[ks][3], pal[ks][3]);
        }

        // ---- rescale O ----
        #pragma unroll
        for (int na = 0; na < 4; na++) {
            sO[na][0] *= fac[0]; sO[na][1] *= fac[0];
            sO[na][2] *= fac[1]; sO[na][3] *= fac[1];
        }

        // ---- O += P V ----
        #pragma unroll
        for (int ks = 0; ks < 4; ks++) {
            #pragma unroll
            for (int p = 0; p < 2; p++) {
                unsigned bh[4], bl[4];
                ldsm4(bh[0],bh[1],bh[2],bh[3], sptr(Vh + (brow + p*16)*VSTR + ks*16 + bkoff));
                ldsm4(bl[0],bl[1],bl[2],bl[3], sptr(Vl + (brow + p*16)*VSTR + ks*16 + bkoff));
                mma_bf16(sO[2*p],   pah[ks], bh[0], bh[1]);
                mma_bf16(sO[2*p],   pah[ks], bl[0], bl[1]);
                mma_bf16(sO[2*p],   pal[ks], bh[0], bh[1]);
                mma_bf16(sO[2*p+1], pah[ks], bh[2], bh[3]);
                mma_bf16(sO[2*p+1], pah[ks], bl[2], bl[3]);
                mma_bf16(sO[2*p+1], pal[ks], bh[2], bh[3]);
            }
        }
    }

    // ---- normalize + store ----
    int r0 = lane >> 2;
    float inv0 = 1.f / lrow[0];
    float inv1 = 1.f / lrow[1];
    #pragma unroll
    for (int na = 0; na < 4; na++) {
        int col = h*DH + na*8 + c2;
        int qrow = q0 + wid*16 + r0;
        if (qrow < LL)
            *(float2*)(out + (size_t)(b*LL + qrow)*DD + col)
                = make_float2(sO[na][0]*inv0, sO[na][1]*inv0);
        if (qrow + 8 < LL)
            *(float2*)(out + (size_t)(b*LL + qrow + 8)*DD + col)
                = make_float2(sO[na][2]*inv1, sO[na][3]*inv1);
    }
}

// ---------------- residual add + LayerNorm (warp per row, shuffle-only) -----
__global__ void __launch_bounds__(256) add_ln_kernel(
    const float* __restrict__ x, const float* __restrict__ y,
    const float* __restrict__ gam, const float* __restrict__ bet,
    float* __restrict__ out, int doadd)
{
    int warp = threadIdx.x >> 5, lane = threadIdx.x & 31;
    int row = blockIdx.x*8 + warp;
    const float* xr = x + (size_t)row*DD + lane*8;
    float v[8];
    float4 va = *(const float4*)(xr);
    float4 vb = *(const float4*)(xr + 4);
    v[0]=va.x; v[1]=va.y; v[2]=va.z; v[3]=va.w;
    v[4]=vb.x; v[5]=vb.y; v[6]=vb.z; v[7]=vb.w;
    if (doadd) {
        const float* yr = y + (size_t)row*DD + lane*8;
        float4 ya = *(const float4*)(yr);
        float4 yb = *(const float4*)(yr + 4);
        v[0]+=ya.x; v[1]+=ya.y; v[2]+=ya.z; v[3]+=ya.w;
        v[4]+=yb.x; v[5]+=yb.y; v[6]+=yb.z; v[7]+=yb.w;
    }
    float s = 0.f;
    #pragma unroll
    for (int i=0;i<8;i++) s += v[i];
    #pragma unroll
    for (int off=16; off; off>>=1) s += __shfl_xor_sync(0xffffffffu, s, off);
    float mean = s * (1.f/DD);
    float s2 = 0.f;
    #pragma unroll
    for (int i=0;i<8;i++) { v[i] -= mean; s2 += v[i]*v[i]; }
    #pragma unroll
    for (int off=16; off; off>>=1) s2 += __shfl_xor_sync(0xffffffffu, s2, off);
    float rstd = rsqrtf(s2 * (1.f/DD) + 1e-5f);
    const float* gp = gam + lane*8;
    const float* bp = bet + lane*8;
    float4 ga = *(const float4*)(gp);
    float4 gb = *(const float4*)(gp+4);
    float4 ba = *(const float4*)(bp);
    float4 bb = *(const float4*)(bp+4);
    float g[8] = {ga.x,ga.y,ga.z,ga.w,gb.x,gb.y,gb.z,gb.w};
    float be[8] = {ba.x,ba.y,ba.z,ba.w,bb.x,bb.y,bb.z,bb.w};
    float o[8];
    #pragma unroll
    for (int i=0;i<8;i++) o[i] = v[i]*rstd*g[i] + be[i];
    float* op = out + (size_t)row*DD + lane*8;
    *(float4*)(op)   = make_float4(o[0],o[1],o[2],o[3]);
    *(float4*)(op+4) = make_float4(o[4],o[5],o[6],o[7]);
}

// ---------------- launch ----------------
extern "C" void kernel_launch(void* const* d_in, const int* in_sizes, int n_in,
                              void* d_out, int out_size)
{
    const float* x_img          = (const float*)d_in[0];
    const void*  pmask          = (const void*)d_in[1];
    const int*   valid_idx      = (const int*)d_in[2];
    const float* pe_w           = (const float*)d_in[3];
    const float* pe_b           = (const float*)d_in[4];
    const float* spos           = (const float*)d_in[5];
    const float* Wqkv           = (const float*)d_in[6];
    const float* bqkv           = (const float*)d_in[7];
    const float* Wo             = (const float*)d_in[8];
    const float* bo             = (const float*)d_in[9];
    const float* ln1s           = (const float*)d_in[10];
    const float* ln1b           = (const float*)d_in[11];
    const float* W1             = (const float*)d_in[12];
    const float* b1             = (const float*)d_in[13];
    const float* W2             = (const float*)d_in[14];
    const float* b2             = (const float*)d_in[15];
    const float* ln2s           = (const float*)d_in[16];
    const float* ln2b           = (const float*)d_in[17];
    const float* nfs            = (const float*)d_in[18];
    const float* nfb            = (const float*)d_in[19];
    float* out = (float*)d_out;

    float *px, *pqkv, *patt, *py, *pff;
    cudaGetSymbolAddress((void**)&px,   g_x);
    cudaGetSymbolAddress((void**)&pqkv, g_qkv);
    cudaGetSymbolAddress((void**)&patt, g_att);
    cudaGetSymbolAddress((void**)&py,   g_y);
    cudaGetSymbolAddress((void**)&pff,  g_ff);

    cudaFuncSetAttribute(attn_kernel, cudaFuncAttributeMaxDynamicSharedMemorySize, ATT_SMEM);
    cudaFuncSetAttribute(gemm_kernel, cudaFuncAttributeMaxDynamicSharedMemorySize, GEMM_SMEM);

    build_vis_kernel<<<(BB*TT+255)/256, 256>>>(pmask, valid_idx);
    embed_kernel<<<MM/16, 256>>>(x_img, valid_idx, pe_w, pe_b, spos);

    for (int i = 0; i < NLAYERS; i++) {
        gemm_kernel<<<dim3(MM/128, 3*DD/128), 256, GEMM_SMEM>>>(px, Wqkv + i*3*DD*DD, bqkv + i*3*DD, pqkv, 3*DD, DD, 0);
        attn_kernel<<<dim3((LL+127)/128, BB*NHEAD), 256, ATT_SMEM>>>(pqkv, patt);
        gemm_kernel<<<dim3(MM/128, DD/128), 256, GEMM_SMEM>>>(patt, Wo + i*DD*DD, bo + i*DD, py, DD, DD, 0);
        add_ln_kernel<<<MM/8, 256>>>(px, py, ln1s + i*DD, ln1b + i*DD, px, 1);
        gemm_kernel<<<dim3(MM/128, DFF/128), 256, GEMM_SMEM>>>(px, W1 + i*DFF*DD, b1 + i*DFF, pff, DFF, DD, 1);
        gemm_kernel<<<dim3(MM/128, DD/128), 256, GEMM_SMEM>>>(pff, W2 + i*DD*DFF, b2 + i*DD, py, DD, DFF, 0);
        add_ln_kernel<<<MM/8, 256>>>(px, py, ln2s + i*DD, ln2b + i*DD, px, 1);
    }
    add_ln_kernel<<<MM/8, 256>>>(px, px, nfs, nfb, out, 0);
}

// round 7
// speedup vs baseline: 2.7373x; 1.0688x over previous
#include <cuda_runtime.h>
#include <cuda_bf16.h>
#include <math.h>
#include <stdint.h>

#define BB 8
#define TT 90
#define HIMG 290
#define WIMG 180
#define PS 10
#define NWP 18
#define NP 522
#define PD 100
#define NV 94
#define KVIS 24
#define LL 2160
#define DD 256
#define NHEAD 8
#define DH 32
#define NLAYERS 6
#define DFF 1024
#define MM (BB*LL)   /* 17280 */
#define LTP 2176     /* LL padded to 68*32 */
#define ASCALE 0.17677669529663687f

// per-layer weight segment offsets (elements), layer stride
#define WOFS_QKV 0
#define WOFS_O   196608
#define WOFS_1   262144
#define WOFS_2   524288
#define WLAYER   786432
#define WTOTAL   (6*WLAYER)

// ---------------- scratch (no cudaMalloc allowed) ----------------
__device__ float g_x[MM*DD];
__device__ float g_qkv[MM*3*DD];
__device__ float g_y[MM*DD];
__device__ __nv_bfloat16 g_xh[MM*DD],  g_xl[MM*DD];
__device__ __nv_bfloat16 g_atth[MM*DD], g_attl[MM*DD];
__device__ __nv_bfloat16 g_ffh[MM*DFF], g_ffl[MM*DFF];
__device__ __nv_bfloat16 g_qh[BB*NHEAD*LL*DH], g_ql[BB*NHEAD*LL*DH];
__device__ __nv_bfloat16 g_kh[BB*NHEAD*LL*DH], g_kl[BB*NHEAD*LL*DH];
__device__ __nv_bfloat16 g_vth[BB*NHEAD*DH*LTP], g_vtl[BB*NHEAD*DH*LTP];
__device__ __nv_bfloat16 g_wh[WTOTAL], g_wl[WTOTAL];
__device__ int   g_tokv[MM];

// ---------------- mma / ldmatrix / bf16-split helpers ----------------
__device__ __forceinline__ unsigned sptr(const void* p) {
    return (unsigned)__cvta_generic_to_shared(p);
}
__device__ __forceinline__ void ldsm4(unsigned &r0, unsigned &r1, unsigned &r2, unsigned &r3, unsigned addr) {
    asm volatile("ldmatrix.sync.aligned.m8n8.x4.shared.b16 {%0,%1,%2,%3}, [%4];"
                 : "=r"(r0), "=r"(r1), "=r"(r2), "=r"(r3) : "r"(addr));
}
__device__ __forceinline__ void mma_bf16(float* c, const unsigned* a, unsigned b0, unsigned b1) {
    asm volatile("mma.sync.aligned.m16n8k16.row.col.f32.bf16.bf16.f32 "
                 "{%0,%1,%2,%3}, {%4,%5,%6,%7}, {%8,%9}, {%0,%1,%2,%3};"
                 : "+f"(c[0]), "+f"(c[1]), "+f"(c[2]), "+f"(c[3])
                 : "r"(a[0]), "r"(a[1]), "r"(a[2]), "r"(a[3]), "r"(b0), "r"(b1));
}
__device__ __forceinline__ void split2(float x0, float x1, unsigned &h, unsigned &l) {
    __nv_bfloat16 h0 = __float2bfloat16(x0), h1 = __float2bfloat16(x1);
    float r0 = x0 - __bfloat162float(h0), r1 = x1 - __bfloat162float(h1);
    __nv_bfloat16 l0 = __float2bfloat16(r0), l1 = __float2bfloat16(r1);
    h = (unsigned)__bfloat16_as_ushort(h0) | ((unsigned)__bfloat16_as_ushort(h1) << 16);
    l = (unsigned)__bfloat16_as_ushort(l0) | ((unsigned)__bfloat16_as_ushort(l1) << 16);
}

// ---------------- token list ----------------
__global__ void build_vis_kernel(const void* __restrict__ mask_raw,
                                 const int* __restrict__ valid_idx)
{
    int bt = blockIdx.x*blockDim.x + threadIdx.x;
    if (bt >= BB*TT) return;
    const int*   mi = (const int*)mask_raw;
    const float* mf = (const float*)mask_raw;
    const unsigned char* mb = (const unsigned char*)mask_raw;
    int is_int = 1;
    for (int j = 0; j < NP; j++) { int w = mi[j]; if (w != 0 && w != 1) { is_int = 0; break; } }
    int is_float = 0;
    if (!is_int) {
        is_float = 1;
        for (int j = 0; j < NP; j++) { float w = mf[j]; if (w != 0.0f && w != 1.0f) { is_float = 0; break; } }
    }
    int base = bt*KVIS, cnt = 0;
    for (int v = 0; v < NV; v++) {
        int idx = bt*NP + valid_idx[v];
        int masked;
        if (is_int)        masked = (mi[idx] != 0);
        else if (is_float) masked = (mf[idx] != 0.0f);
        else               masked = (mb[idx] != 0);
        if (!masked) { if (cnt < KVIS) g_tokv[base+cnt] = v; cnt++; }
    }
}

// ---------------- patchify + patch embed + pos encodings ----------------
__global__ void __launch_bounds__(256) embed_kernel(
    const float* __restrict__ img, const int* __restrict__ valid_idx,
    const float* __restrict__ Wpe, const float* __restrict__ bpe,
    const float* __restrict__ spos)
{
    __shared__ float pix[16][PD];
    __shared__ float wsm[DD][27];
    __shared__ int sm_v[16], sm_t[16], sm_off[16];
    int tid = threadIdx.x;
    int m0 = blockIdx.x * 16;
    if (tid < 16) {
        int m = m0 + tid;
        int b = m / LL;
        int l = m - b*LL;
        int t = l / KVIS;
        int v = g_tokv[m];
        int patch = valid_idx[v];
        int hp = patch / NWP, wp = patch - hp*NWP;
        sm_v[tid] = v; sm_t[tid] = t;
        sm_off[tid] = ((b*TT + t)*HIMG + hp*PS)*WIMG + wp*PS;
    }
    __syncthreads();
    for (int j = tid; j < 16*PD; j += 256) {
        int tok = j / PD, pd = j - tok*PD;
        int ph = pd / PS, pw = pd - ph*PS;
        pix[tok][pd] = img[sm_off[tok] + ph*WIMG + pw];
    }
    float acc[16];
    #pragma unroll
    for (int i = 0; i < 16; i++) acc[i] = 0.f;
    for (int k0 = 0; k0 < PD; k0 += 25) {
        __syncthreads();
        for (int j = tid; j < DD*25; j += 256) {
            int dd = j / 25, kk = j - dd*25;
            wsm[dd][kk] = Wpe[dd*PD + k0 + kk];
        }
        __syncthreads();
        #pragma unroll
        for (int kk = 0; kk < 25; kk++) {
            float w = wsm[tid][kk];
            #pragma unroll
            for (int tok = 0; tok < 16; tok++)
                acc[tok] = fmaf(w, pix[tok][k0+kk], acc[tok]);
        }
    }
    int d = tid;
    float freq = expf((float)(d & ~1) * (-9.210340371976184f / 256.f));
    float pb = bpe[d];
    #pragma unroll
    for (int tok = 0; tok < 16; tok++) {
        float val = (float)sm_t[tok] * freq;
        float pe = (d & 1) ? cosf(val) : sinf(val);
        g_x[(m0+tok)*DD + d] = acc[tok] + pb + spos[sm_v[tok]*DD + d] + pe;
    }
}

// ---------------- one-time prep: weights -> hi/lo bf16, layer-major --------
__global__ void prep_weights_kernel(const float* __restrict__ Wqkv, const float* __restrict__ Wo,
                                    const float* __restrict__ W1, const float* __restrict__ W2)
{
    int i = blockIdx.x*blockDim.x + threadIdx.x;
    int layer = i / WLAYER;
    int r = i - layer*WLAYER;
    float v;
    if      (r < WOFS_O) v = Wqkv[layer*196608 + r];
    else if (r < WOFS_1) v = Wo[layer*65536 + r - WOFS_O];
    else if (r < WOFS_2) v = W1[layer*262144 + r - WOFS_1];
    else                 v = W2[layer*262144 + r - WOFS_2];
    __nv_bfloat16 hh = __float2bfloat16(v);
    g_wh[i] = hh;
    g_wl[i] = __float2bfloat16(v - __bfloat162float(hh));
}

// ---------------- x fp32 -> hi/lo bf16 (after embed only) ----------------
__global__ void cvt_x_kernel()
{
    int i = blockIdx.x*blockDim.x + threadIdx.x;   // over MM*DD/2
    float2 v = ((const float2*)g_x)[i];
    unsigned h, l; split2(v.x, v.y, h, l);
    ((unsigned*)g_xh)[i] = h;
    ((unsigned*)g_xl)[i] = l;
}

// ---------------- per-layer prep: qkv fp32 -> Q/K hi/lo + V^T hi/lo --------
// grid (68, B*H), 256 thr. chunk = 32 tokens. Q gets ASCALE folded in.
__global__ void __launch_bounds__(256) prep_qkv_kernel()
{
    __shared__ float vs[32][33];
    int bh = blockIdx.y;
    int b = bh >> 3, h = bh & 7;
    int l0 = blockIdx.x * 32;
    int tid = threadIdx.x;
    const float* qbase = g_qkv + (size_t)b*LL*768 + h*32;

    // Q (m=0, scaled) and K (m=1)
    #pragma unroll
    for (int m = 0; m < 2; m++) {
        int j = tid;
        #pragma unroll
        for (int it = 0; it < 2; it++, j += 256) {
            int l = l0 + (j >> 4), dp = j & 15;
            if (l < LL) {
                float2 v = *(const float2*)(qbase + (size_t)l*768 + m*256 + dp*2);
                if (m == 0) { v.x *= ASCALE; v.y *= ASCALE; }
                unsigned hw, lw; split2(v.x, v.y, hw, lw);
                size_t o = ((size_t)bh*LL + l)*16 + dp;
                if (m == 0) { ((unsigned*)g_qh)[o] = hw; ((unsigned*)g_ql)[o] = lw; }
                else        { ((unsigned*)g_kh)[o] = hw; ((unsigned*)g_kl)[o] = lw; }
            }
            j -= 256;  // restore (loop adds again)
            j += 256;
        }
    }
    // V: load rows, transpose through smem, write V^T (zeros in tail pad)
    {
        int l = l0 + (tid >> 3), dq = tid & 7;
        float4 v = make_float4(0.f,0.f,0.f,0.f);
        if (l < LL) v = *(const float4*)(qbase + (size_t)l*768 + 512 + dq*4);
        int ll = tid >> 3;
        vs[dq*4+0][ll] = v.x; vs[dq*4+1][ll] = v.y;
        vs[dq*4+2][ll] = v.z; vs[dq*4+3][ll] = v.w;
    }
    __syncthreads();
    {
        int d = tid >> 3, c = tid & 7;
        float f0 = vs[d][c*4+0], f1 = vs[d][c*4+1], f2 = vs[d][c*4+2], f3 = vs[d][c*4+3];
        unsigned h0, w0, h1, w1;
        split2(f0, f1, h0, w0);
        split2(f2, f3, h1, w1);
        size_t o = (((size_t)bh*32 + d)*LTP + l0 + c*4) >> 1;
        ((unsigned*)g_vth)[o]   = h0; ((unsigned*)g_vth)[o+1] = h1;
        ((unsigned*)g_vtl)[o]   = w0; ((unsigned*)g_vtl)[o+1] = w1;
    }
}

// ---------------- bf16-split tensor-core GEMM (pre-split A and W) ----------
// C[m,n] = sum_k A[m,k]*W[n,k] + bias[n].  Block 128x128, BK=16, 256 thr.
#define GSTR 24
#define GEMM_AS (128*GSTR)
#define GEMM_SMEM (2*4*GEMM_AS*2)

__global__ void __launch_bounds__(256,2) gemm_kernel(
    const __nv_bfloat16* __restrict__ Ahg, const __nv_bfloat16* __restrict__ Alg,
    const __nv_bfloat16* __restrict__ Whg, const __nv_bfloat16* __restrict__ Wlg,
    const float* __restrict__ bias,
    float* __restrict__ C, __nv_bfloat16* __restrict__ Ch, __nv_bfloat16* __restrict__ Cl,
    int Ndim, int Kdim, int relu, int outbf)
{
    extern __shared__ __align__(16) char smraw[];
    __nv_bfloat16* smb = (__nv_bfloat16*)smraw;
    int tid = threadIdx.x, lane = tid & 31, wid = tid >> 5;
    int wm = wid >> 1, wn = wid & 1;
    int m0 = blockIdx.x*128, n0 = blockIdx.y*128;
    int lrow = tid >> 1, lk = (tid & 1) << 3;
    const __nv_bfloat16* Ahp = Ahg + (size_t)(m0 + lrow)*Kdim + lk;
    const __nv_bfloat16* Alp = Alg + (size_t)(m0 + lrow)*Kdim + lk;
    const __nv_bfloat16* Whp = Whg + (size_t)(n0 + lrow)*Kdim + lk;
    const __nv_bfloat16* Wlp = Wlg + (size_t)(n0 + lrow)*Kdim + lk;

    float acc[2][8][4];
    #pragma unroll
    for (int i=0;i<2;i++)
        #pragma unroll
        for (int j=0;j<8;j++)
            #pragma unroll
            for (int q=0;q<4;q++) acc[i][j][q]=0.f;

    int arow = wm*32 + (lane & 15);
    int akoff = (lane >> 4) << 3;
    int brow = wn*64 + ((lane >> 4) << 3) + (lane & 7);
    int bkoff = ((lane >> 3) & 1) << 3;

    // prologue
    {
        uint4 a0 = *(const uint4*)(Ahp);
        uint4 a1 = *(const uint4*)(Alp);
        uint4 w0 = *(const uint4*)(Whp);
        uint4 w1 = *(const uint4*)(Wlp);
        __nv_bfloat16* s = smb;
        *(uint4*)(s + 0*GEMM_AS + lrow*GSTR + lk) = a0;
        *(uint4*)(s + 1*GEMM_AS + lrow*GSTR + lk) = a1;
        *(uint4*)(s + 2*GEMM_AS + lrow*GSTR + lk) = w0;
        *(uint4*)(s + 3*GEMM_AS + lrow*GSTR + lk) = w1;
    }
    __syncthreads();

    int buf = 0;
    for (int k0 = 0; k0 < Kdim; k0 += 16) {
        int more = (k0 + 16 < Kdim);
        uint4 na0, na1, nw0, nw1;
        if (more) {
            na0 = *(const uint4*)(Ahp + k0 + 16);
            na1 = *(const uint4*)(Alp + k0 + 16);
            nw0 = *(const uint4*)(Whp + k0 + 16);
            nw1 = *(const uint4*)(Wlp + k0 + 16);
        }
        __nv_bfloat16* Ah = smb + buf*4*GEMM_AS;
        __nv_bfloat16* Al = Ah + GEMM_AS;
        __nv_bfloat16* Wh = Al + GEMM_AS;
        __nv_bfloat16* Wl = Wh + GEMM_AS;

        unsigned ah0[4], al0[4], ah1[4], al1[4];
        ldsm4(ah0[0],ah0[1],ah0[2],ah0[3], sptr(Ah + arow*GSTR + akoff));
        ldsm4(al0[0],al0[1],al0[2],al0[3], sptr(Al + arow*GSTR + akoff));
        ldsm4(ah1[0],ah1[1],ah1[2],ah1[3], sptr(Ah + (arow+16)*GSTR + akoff));
        ldsm4(al1[0],al1[1],al1[2],al1[3], sptr(Al + (arow+16)*GSTR + akoff));

        #pragma unroll
        for (int p = 0; p < 4; p++) {
            unsigned bh[4], bl[4];
            ldsm4(bh[0],bh[1],bh[2],bh[3], sptr(Wh + (brow + p*16)*GSTR + bkoff));
            ldsm4(bl[0],bl[1],bl[2],bl[3], sptr(Wl + (brow + p*16)*GSTR + bkoff));
            mma_bf16(acc[0][2*p],   ah0, bh[0], bh[1]);
            mma_bf16(acc[0][2*p],   ah0, bl[0], bl[1]);
            mma_bf16(acc[0][2*p],   al0, bh[0], bh[1]);
            mma_bf16(acc[0][2*p+1], ah0, bh[2], bh[3]);
            mma_bf16(acc[0][2*p+1], ah0, bl[2], bl[3]);
            mma_bf16(acc[0][2*p+1], al0, bh[2], bh[3]);
            mma_bf16(acc[1][2*p],   ah1, bh[0], bh[1]);
            mma_bf16(acc[1][2*p],   ah1, bl[0], bl[1]);
            mma_bf16(acc[1][2*p],   al1, bh[0], bh[1]);
            mma_bf16(acc[1][2*p+1], ah1, bh[2], bh[3]);
            mma_bf16(acc[1][2*p+1], ah1, bl[2], bl[3]);
            mma_bf16(acc[1][2*p+1], al1, bh[2], bh[3]);
        }

        if (more) {
            __nv_bfloat16* s = smb + (buf^1)*4*GEMM_AS;
            *(uint4*)(s + 0*GEMM_AS + lrow*GSTR + lk) = na0;
            *(uint4*)(s + 1*GEMM_AS + lrow*GSTR + lk) = na1;
            *(uint4*)(s + 2*GEMM_AS + lrow*GSTR + lk) = nw0;
            *(uint4*)(s + 3*GEMM_AS + lrow*GSTR + lk) = nw1;
            __syncthreads();
        }
        buf ^= 1;
    }

    // epilogue
    int r0 = lane >> 2;
    int c2 = (lane & 3) << 1;
    #pragma unroll
    for (int ma = 0; ma < 2; ma++) {
        #pragma unroll
        for (int na = 0; na < 8; na++) {
            int col = n0 + wn*64 + na*8 + c2;
            float2 bsv = *(const float2*)(bias + col);
            float v0 = acc[ma][na][0] + bsv.x;
            float v1 = acc[ma][na][1] + bsv.y;
            float v2 = acc[ma][na][2] + bsv.x;
            float v3 = acc[ma][na][3] + bsv.y;
            if (relu) {
                v0 = fmaxf(v0,0.f); v1 = fmaxf(v1,0.f);
                v2 = fmaxf(v2,0.f); v3 = fmaxf(v3,0.f);
            }
            int row = m0 + wm*32 + ma*16 + r0;
            if (outbf) {
                unsigned hw, lw;
                size_t o = ((size_t)row*Ndim + col) >> 1;
                split2(v0, v1, hw, lw);
                ((unsigned*)Ch)[o] = hw; ((unsigned*)Cl)[o] = lw;
                o = ((size_t)(row+8)*Ndim + col) >> 1;
                split2(v2, v3, hw, lw);
                ((unsigned*)Ch)[o] = hw; ((unsigned*)Cl)[o] = lw;
            } else {
                *(float2*)(C + (size_t)row*Ndim + col) = make_float2(v0, v1);
                *(float2*)(C + (size_t)(row+8)*Ndim + col) = make_float2(v2, v3);
            }
        }
    }
}

// ---------------- flash attention, pre-split operands ----------------
#define ATSTR 40
#define VSTR 72
#define ATT_SMEM ((2*128*ATSTR + 2*64*ATSTR + 2*32*VSTR)*2)

__global__ void __launch_bounds__(256,2) attn_kernel(__nv_bfloat16* __restrict__ outh,
                                                     __nv_bfloat16* __restrict__ outl)
{
    extern __shared__ __align__(16) char smraw[];
    __nv_bfloat16* Qhs = (__nv_bfloat16*)smraw;      // [128][ATSTR]
    __nv_bfloat16* Qls = Qhs + 128*ATSTR;
    __nv_bfloat16* Khs = Qls + 128*ATSTR;            // [64][ATSTR]
    __nv_bfloat16* Kls = Khs + 64*ATSTR;
    __nv_bfloat16* Vhs = Kls + 64*ATSTR;             // [32][VSTR]
    __nv_bfloat16* Vls = Vhs + 32*VSTR;

    int tid = threadIdx.x, lane = tid & 31, wid = tid >> 5;
    int q0 = blockIdx.x * 128;
    int bh = blockIdx.y;
    int b = bh >> 3, h = bh & 7;

    // ---- copy Q tile: 128 rows x 32 bf16 x {hi,lo} = 4 x 256 uint4 chunks --
    #pragma unroll
    for (int it = 0; it < 4; it++) {
        int idx = it*256 + tid;            // 0..1023
        int bsel = idx >> 9;               // 0=hi, 1=lo
        int rem = idx & 511;
        int r = rem >> 2, c = rem & 3;     // row 0..127, chunk of 8 elements
        int qrow = q0 + r;
        uint4 v = make_uint4(0,0,0,0);
        if (qrow < LL) {
            size_t o = ((size_t)bh*LL + qrow)*32 + c*8;
            v = bsel ? *(const uint4*)(g_ql + o) : *(const uint4*)(g_qh + o);
        }
        __nv_bfloat16* dp = bsel ? Qls : Qhs;
        *(uint4*)(dp + r*ATSTR + c*8) = v;
    }

    int arow = wid*16 + (lane & 15);
    int akoff = (lane >> 4) << 3;
    int brow = ((lane >> 4) << 3) + (lane & 7);
    int bkoff = ((lane >> 3) & 1) << 3;
    int c2 = (lane & 3) << 1;

    float sO[4][4];
    #pragma unroll
    for (int i=0;i<4;i++)
        #pragma unroll
        for (int j=0;j<4;j++) sO[i][j]=0.f;
    float mrow[2] = {-1e30f, -1e30f};
    float lrow[2] = {0.f, 0.f};

    for (int kt = 0; kt < 34; kt++) {
        int k0t = kt*64;
        __syncthreads();
        // ---- copy K tile: 64 rows x 32 bf16 x {hi,lo} = 2 x 256 chunks ----
        #pragma unroll
        for (int it = 0; it < 2; it++) {
            int idx = it*256 + tid;        // 0..511
            int bsel = idx >> 8;
            int rem = idx & 255;
            int r = rem >> 2, c = rem & 3;
            int krow = k0t + r;
            uint4 v = make_uint4(0,0,0,0);
            if (krow < LL) {
                size_t o = ((size_t)bh*LL + krow)*32 + c*8;
                v = bsel ? *(const uint4*)(g_kl + o) : *(const uint4*)(g_kh + o);
            }
            __nv_bfloat16* dp = bsel ? Kls : Khs;
            *(uint4*)(dp + r*ATSTR + c*8) = v;
        }
        // ---- copy V^T tile: 32 d-rows x 64 tokens x {hi,lo} ----
        #pragma unroll
        for (int it = 0; it < 2; it++) {
            int idx = it*256 + tid;
            int bsel = idx >> 8, rem = idx & 255, dd = rem >> 3, c = rem & 7;
            size_t o = ((size_t)bh*32 + dd)*LTP + k0t + c*8;
            uint4 v = bsel ? *(const uint4*)(g_vtl + o) : *(const uint4*)(g_vth + o);
            __nv_bfloat16* dp = bsel ? Vls : Vhs;
            *(uint4*)(dp + dd*VSTR + c*8) = v;
        }
        __syncthreads();

        // ---- S = Q K^T ----
        float s[8][4];
        #pragma unroll
        for (int i=0;i<8;i++)
            #pragma unroll
            for (int j=0;j<4;j++) s[i][j]=0.f;
        #pragma unroll
        for (int ks = 0; ks < 2; ks++) {
            unsigned ah[4], al[4];
            ldsm4(ah[0],ah[1],ah[2],ah[3], sptr(Qhs + arow*ATSTR + ks*16 + akoff));
            ldsm4(al[0],al[1],al[2],al[3], sptr(Qls + arow*ATSTR + ks*16 + akoff));
            #pragma unroll
            for (int p = 0; p < 4; p++) {
                unsigned bhr[4], blr[4];
                ldsm4(bhr[0],bhr[1],bhr[2],bhr[3], sptr(Khs + (brow + p*16)*ATSTR + ks*16 + bkoff));
                ldsm4(blr[0],blr[1],blr[2],blr[3], sptr(Kls + (brow + p*16)*ATSTR + ks*16 + bkoff));
                mma_bf16(s[2*p],   ah, bhr[0], bhr[1]);
                mma_bf16(s[2*p],   ah, blr[0], blr[1]);
                mma_bf16(s[2*p],   al, bhr[0], bhr[1]);
                mma_bf16(s[2*p+1], ah, bhr[2], bhr[3]);
                mma_bf16(s[2*p+1], ah, blr[2], blr[3]);
                mma_bf16(s[2*p+1], al, bhr[2], bhr[3]);
            }
        }

        // ---- online softmax (scale pre-folded into Q) ----
        int tail = (k0t + 64 > LL);
        float fac[2];
        #pragma unroll
        for (int hf = 0; hf < 2; hf++) {
            float vmax = -1e30f;
            #pragma unroll
            for (int na = 0; na < 8; na++) {
                float v0 = s[na][2*hf];
                float v1 = s[na][2*hf+1];
                if (tail) {
                    if (k0t + na*8 + c2     >= LL) v0 = -1e30f;
                    if (k0t + na*8 + c2 + 1 >= LL) v1 = -1e30f;
                }
                s[na][2*hf] = v0; s[na][2*hf+1] = v1;
                vmax = fmaxf(vmax, fmaxf(v0, v1));
            }
            vmax = fmaxf(vmax, __shfl_xor_sync(0xffffffffu, vmax, 1));
            vmax = fmaxf(vmax, __shfl_xor_sync(0xffffffffu, vmax, 2));
            float mnew = fmaxf(mrow[hf], vmax);
            fac[hf] = __expf(mrow[hf] - mnew);
            mrow[hf] = mnew;
            float ps = 0.f;
            #pragma unroll
            for (int na = 0; na < 8; na++) {
                float p0 = __expf(s[na][2*hf]   - mnew);
                float p1 = __expf(s[na][2*hf+1] - mnew);
                s[na][2*hf] = p0; s[na][2*hf+1] = p1;
                ps += p0 + p1;
            }
            ps += __shfl_xor_sync(0xffffffffu, ps, 1);
            ps += __shfl_xor_sync(0xffffffffu, ps, 2);
            lrow[hf] = lrow[hf]*fac[hf] + ps;
        }

        // ---- pack P fragments ----
        unsigned pah[4][4], pal[4][4];
        #pragma unroll
        for (int ks = 0; ks < 4; ks++) {
            split2(s[2*ks][0],   s[2*ks][1],   pah[ks][0], pal[ks][0]);
            split2(s[2*ks][2],   s[2*ks][3],   pah[ks][1], pal[ks][1]);
            split2(s[2*ks+1][0], s[2*ks+1][1], pah[ks][2], pal[ks][2]);
            split2(s[2*ks+1][2], s[2*ks+1][3], pah[ks][3], pal[ks][3]);
        }

        // ---- rescale O ----
        #pragma unroll
        for (int na = 0; na < 4; na++) {
            sO[na][0] *= fac[0]; sO[na][1] *= fac[0];
            sO[na][2] *= fac[1]; sO[na][3] *= fac[1];
        }

        // ---- O += P V ----
        #pragma unroll
        for (int ks = 0; ks < 4; ks++) {
            #pragma unroll
            for (int p = 0; p < 2; p++) {
                unsigned bhr[4], blr[4];
                ldsm4(bhr[0],bhr[1],bhr[2],bhr[3], sptr(Vhs + (brow + p*16)*VSTR + ks*16 + bkoff));
                ldsm4(blr[0],blr[1],blr[2],blr[3], sptr(Vls + (brow + p*16)*VSTR + ks*16 + bkoff));
                mma_bf16(sO[2*p],   pah[ks], bhr[0], bhr[1]);
                mma_bf16(sO[2*p],   pah[ks], blr[0], blr[1]);
                mma_bf16(sO[2*p],   pal[ks], bhr[0], bhr[1]);
                mma_bf16(sO[2*p+1], pah[ks], bhr[2], bhr[3]);
                mma_bf16(sO[2*p+1], pah[ks], blr[2], blr[3]);
                mma_bf16(sO[2*p+1], pal[ks], bhr[2], bhr[3]);
            }
        }
    }

    // ---- normalize + store hi/lo bf16 ----
    int r0 = lane >> 2;
    float inv0 = 1.f / lrow[0];
    float inv1 = 1.f / lrow[1];
    #pragma unroll
    for (int na = 0; na < 4; na++) {
        int col = h*DH + na*8 + c2;
        int qrow = q0 + wid*16 + r0;
        unsigned hw, lw;
        if (qrow < LL) {
            split2(sO[na][0]*inv0, sO[na][1]*inv0, hw, lw);
            size_t o = (((size_t)(b*LL + qrow))*DD + col) >> 1;
            ((unsigned*)outh)[o] = hw; ((unsigned*)outl)[o] = lw;
        }
        if (qrow + 8 < LL) {
            split2(sO[na][2]*inv1, sO[na][3]*inv1, hw, lw);
            size_t o = (((size_t)(b*LL + qrow + 8))*DD + col) >> 1;
            ((unsigned*)outh)[o] = hw; ((unsigned*)outl)[o] = lw;
        }
    }
}

// ---------------- residual add + LayerNorm (warp/row) + optional bf16 split -
__global__ void __launch_bounds__(256) add_ln_kernel(
    const float* __restrict__ x, const float* __restrict__ y,
    const float* __restrict__ gam, const float* __restrict__ bet,
    float* __restrict__ out, __nv_bfloat16* __restrict__ oh, __nv_bfloat16* __restrict__ ol,
    int doadd)
{
    int warp = threadIdx.x >> 5, lane = threadIdx.x & 31;
    int row = blockIdx.x*8 + warp;
    const float* xr = x + (size_t)row*DD + lane*8;
    float v[8];
    float4 va = *(const float4*)(xr);
    float4 vb = *(const float4*)(xr + 4);
    v[0]=va.x; v[1]=va.y; v[2]=va.z; v[3]=va.w;
    v[4]=vb.x; v[5]=vb.y; v[6]=vb.z; v[7]=vb.w;
    if (doadd) {
        const float* yr = y + (size_t)row*DD + lane*8;
        float4 ya = *(const float4*)(yr);
        float4 yb = *(const float4*)(yr + 4);
        v[0]+=ya.x; v[1]+=ya.y; v[2]+=ya.z; v[3]+=ya.w;
        v[4]+=yb.x; v[5]+=yb.y; v[6]+=yb.z; v[7]+=yb.w;
    }
    float s = 0.f;
    #pragma unroll
    for (int i=0;i<8;i++) s += v[i];
    #pragma unroll
    for (int off=16; off; off>>=1) s += __shfl_xor_sync(0xffffffffu, s, off);
    float mean = s * (1.f/DD);
    float s2 = 0.f;
    #pragma unroll
    for (int i=0;i<8;i++) { v[i] -= mean; s2 += v[i]*v[i]; }
    #pragma unroll
    for (int off=16; off; off>>=1) s2 += __shfl_xor_sync(0xffffffffu, s2, off);
    float rstd = rsqrtf(s2 * (1.f/DD) + 1e-5f);
    const float* gp = gam + lane*8;
    const float* bp = bet + lane*8;
    float4 ga = *(const float4*)(gp);
    float4 gb = *(const float4*)(gp+4);
    float4 ba = *(const float4*)(bp);
    float4 bb = *(const float4*)(bp+4);
    float g[8] = {ga.x,ga.y,ga.z,ga.w,gb.x,gb.y,gb.z,gb.w};
    float be[8] = {ba.x,ba.y,ba.z,ba.w,bb.x,bb.y,bb.z,bb.w};
    float o[8];
    #pragma unroll
    for (int i=0;i<8;i++) o[i] = v[i]*rstd*g[i] + be[i];
    float* op = out + (size_t)row*DD + lane*8;
    *(float4*)(op)   = make_float4(o[0],o[1],o[2],o[3]);
    *(float4*)(op+4) = make_float4(o[4],o[5],o[6],o[7]);
    if (oh) {
        unsigned hw[4], lw[4];
        split2(o[0],o[1],hw[0],lw[0]);
        split2(o[2],o[3],hw[1],lw[1]);
        split2(o[4],o[5],hw[2],lw[2]);
        split2(o[6],o[7],hw[3],lw[3]);
        size_t ob = ((size_t)row*DD + lane*8) >> 1;   // in 4B words
        *(uint4*)((unsigned*)oh + ob) = make_uint4(hw[0],hw[1],hw[2],hw[3]);
        *(uint4*)((unsigned*)ol + ob) = make_uint4(lw[0],lw[1],lw[2],lw[3]);
    }
}

// ---------------- launch ----------------
extern "C" void kernel_launch(void* const* d_in, const int* in_sizes, int n_in,
                              void* d_out, int out_size)
{
    const float* x_img          = (const float*)d_in[0];
    const void*  pmask          = (const void*)d_in[1];
    const int*   valid_idx      = (const int*)d_in[2];
    const float* pe_w           = (const float*)d_in[3];
    const float* pe_b           = (const float*)d_in[4];
    const float* spos           = (const float*)d_in[5];
    const float* Wqkv           = (const float*)d_in[6];
    const float* bqkv           = (const float*)d_in[7];
    const float* Wo             = (const float*)d_in[8];
    const float* bo             = (const float*)d_in[9];
    const float* ln1s           = (const float*)d_in[10];
    const float* ln1b           = (const float*)d_in[11];
    const float* W1             = (const float*)d_in[12];
    const float* b1             = (const float*)d_in[13];
    const float* W2             = (const float*)d_in[14];
    const float* b2             = (const float*)d_in[15];
    const float* ln2s           = (const float*)d_in[16];
    const float* ln2b           = (const float*)d_in[17];
    const float* nfs            = (const float*)d_in[18];
    const float* nfb            = (const float*)d_in[19];
    float* out = (float*)d_out;

    float *px, *py;
    __nv_bfloat16 *pxh, *pxl, *path, *patl, *pffh, *pffl, *pwh, *pwl;
    cudaGetSymbolAddress((void**)&px,   g_x);
    cudaGetSymbolAddress((void**)&py,   g_y);
    cudaGetSymbolAddress((void**)&pxh,  g_xh);
    cudaGetSymbolAddress((void**)&pxl,  g_xl);
    cudaGetSymbolAddress((void**)&path, g_atth);
    cudaGetSymbolAddress((void**)&patl, g_attl);
    cudaGetSymbolAddress((void**)&pffh, g_ffh);
    cudaGetSymbolAddress((void**)&pffl, g_ffl);
    cudaGetSymbolAddress((void**)&pwh,  g_wh);
    cudaGetSymbolAddress((void**)&pwl,  g_wl);
    float* pqkv;
    cudaGetSymbolAddress((void**)&pqkv, g_qkv);

    cudaFuncSetAttribute(attn_kernel, cudaFuncAttributeMaxDynamicSharedMemorySize, ATT_SMEM);
    cudaFuncSetAttribute(gemm_kernel, cudaFuncAttributeMaxDynamicSharedMemorySize, GEMM_SMEM);

    prep_weights_kernel<<<WTOTAL/256, 256>>>(Wqkv, Wo, W1, W2);
    build_vis_kernel<<<(BB*TT+255)/256, 256>>>(pmask, valid_idx);
    embed_kernel<<<MM/16, 256>>>(x_img, valid_idx, pe_w, pe_b, spos);
    cvt_x_kernel<<<MM*DD/512, 256>>>();

    for (int i = 0; i < NLAYERS; i++) {
        const __nv_bfloat16* wh = pwh + (size_t)i*WLAYER;
        const __nv_bfloat16* wl = pwl + (size_t)i*WLAYER;
        gemm_kernel<<<dim3(MM/128, 6), 256, GEMM_SMEM>>>(
            pxh, pxl, wh + WOFS_QKV, wl + WOFS_QKV, bqkv + i*768,
            pqkv, nullptr, nullptr, 768, 256, 0, 0);
        prep_qkv_kernel<<<dim3(68, BB*NHEAD), 256>>>();
        attn_kernel<<<dim3(17, BB*NHEAD), 256, ATT_SMEM>>>(path, patl);
        gemm_kernel<<<dim3(MM/128, 2), 256, GEMM_SMEM>>>(
            path, patl, wh + WOFS_O, wl + WOFS_O, bo + i*256,
            py, nullptr, nullptr, 256, 256, 0, 0);
        add_ln_kernel<<<MM/8, 256>>>(px, py, ln1s + i*DD, ln1b + i*DD, px, pxh, pxl, 1);
        gemm_kernel<<<dim3(MM/128, 8), 256, GEMM_SMEM>>>(
            pxh, pxl, wh + WOFS_1, wl + WOFS_1, b1 + i*DFF,
            nullptr, pffh, pffl, 1024, 256, 1, 1);
        gemm_kernel<<<dim3(MM/128, 2), 256, GEMM_SMEM>>>(
            pffh, pffl, wh + WOFS_2, wl + WOFS_2, b2 + i*256,
            py, nullptr, nullptr, 256, 1024, 0, 0);
        add_ln_kernel<<<MM/8, 256>>>(px, py, ln2s + i*DD, ln2b + i*DD, px, pxh, pxl, 1);
    }
    add_ln_kernel<<<MM/8, 256>>>(px, px, nfs, nfb, out, nullptr, nullptr, 0);
}

// round 9
// speedup vs baseline: 2.8031x; 1.0240x over previous
#include <cuda_runtime.h>
#include <cuda_bf16.h>
#include <math.h>
#include <stdint.h>

#define BB 8
#define TT 90
#define HIMG 290
#define WIMG 180
#define PS 10
#define NWP 18
#define NP 522
#define PD 100
#define NV 94
#define KVIS 24
#define LL 2160
#define DD 256
#define NHEAD 8
#define DH 32
#define NLAYERS 6
#define DFF 1024
#define MM (BB*LL)   /* 17280 */
#define LTP 2176     /* LL padded to 68*32 */
#define ASCALE 0.17677669529663687f

// per-layer weight segment offsets (elements), layer stride
#define WOFS_QKV 0
#define WOFS_O   196608
#define WOFS_1   262144
#define WOFS_2   524288
#define WLAYER   786432
#define WTOTAL   (6*WLAYER)

// ---------------- scratch (no cudaMalloc allowed) ----------------
__device__ float g_x[MM*DD];
__device__ float g_qkv[MM*3*DD];
__device__ float g_y[MM*DD];
__device__ __nv_bfloat16 g_xh[MM*DD],  g_xl[MM*DD];
__device__ __nv_bfloat16 g_atth[MM*DD], g_attl[MM*DD];
__device__ __nv_bfloat16 g_ffh[MM*DFF], g_ffl[MM*DFF];
__device__ __nv_bfloat16 g_qh[BB*NHEAD*LL*DH], g_ql[BB*NHEAD*LL*DH];
__device__ __nv_bfloat16 g_kh[BB*NHEAD*LL*DH], g_kl[BB*NHEAD*LL*DH];
__device__ __nv_bfloat16 g_vth[BB*NHEAD*DH*LTP], g_vtl[BB*NHEAD*DH*LTP];
__device__ __nv_bfloat16 g_wh[WTOTAL], g_wl[WTOTAL];
__device__ int   g_tokv[MM];

// ---------------- helpers ----------------
__device__ __forceinline__ unsigned sptr(const void* p) {
    return (unsigned)__cvta_generic_to_shared(p);
}
__device__ __forceinline__ void ldsm4(unsigned &r0, unsigned &r1, unsigned &r2, unsigned &r3, unsigned addr) {
    asm volatile("ldmatrix.sync.aligned.m8n8.x4.shared.b16 {%0,%1,%2,%3}, [%4];"
                 : "=r"(r0), "=r"(r1), "=r"(r2), "=r"(r3) : "r"(addr));
}
__device__ __forceinline__ void mma_bf16(float* c, const unsigned* a, unsigned b0, unsigned b1) {
    asm volatile("mma.sync.aligned.m16n8k16.row.col.f32.bf16.bf16.f32 "
                 "{%0,%1,%2,%3}, {%4,%5,%6,%7}, {%8,%9}, {%0,%1,%2,%3};"
                 : "+f"(c[0]), "+f"(c[1]), "+f"(c[2]), "+f"(c[3])
                 : "r"(a[0]), "r"(a[1]), "r"(a[2]), "r"(a[3]), "r"(b0), "r"(b1));
}
__device__ __forceinline__ void split2(float x0, float x1, unsigned &h, unsigned &l) {
    __nv_bfloat16 h0 = __float2bfloat16(x0), h1 = __float2bfloat16(x1);
    float r0 = x0 - __bfloat162float(h0), r1 = x1 - __bfloat162float(h1);
    __nv_bfloat16 l0 = __float2bfloat16(r0), l1 = __float2bfloat16(r1);
    h = (unsigned)__bfloat16_as_ushort(h0) | ((unsigned)__bfloat16_as_ushort(h1) << 16);
    l = (unsigned)__bfloat16_as_ushort(l0) | ((unsigned)__bfloat16_as_ushort(l1) << 16);
}
__device__ __forceinline__ void cp16(uint32_t dst, const void* src) {
    asm volatile("cp.async.cg.shared.global [%0], [%1], 16;" :: "r"(dst), "l"(src) : "memory");
}
__device__ __forceinline__ void cp16p(uint32_t dst, const void* src, int pred) {
    int sz = pred ? 16 : 0;
    asm volatile("cp.async.cg.shared.global [%0], [%1], 16, %2;" :: "r"(dst), "l"(src), "r"(sz) : "memory");
}
#define CP_COMMIT() asm volatile("cp.async.commit_group;" ::: "memory")
#define CP_WAIT1()  asm volatile("cp.async.wait_group 1;" ::: "memory")

// ---------------- token list ----------------
__global__ void build_vis_kernel(const void* __restrict__ mask_raw,
                                 const int* __restrict__ valid_idx)
{
    int bt = blockIdx.x*blockDim.x + threadIdx.x;
    if (bt >= BB*TT) return;
    const int*   mi = (const int*)mask_raw;
    const float* mf = (const float*)mask_raw;
    const unsigned char* mb = (const unsigned char*)mask_raw;
    int is_int = 1;
    for (int j = 0; j < NP; j++) { int w = mi[j]; if (w != 0 && w != 1) { is_int = 0; break; } }
    int is_float = 0;
    if (!is_int) {
        is_float = 1;
        for (int j = 0; j < NP; j++) { float w = mf[j]; if (w != 0.0f && w != 1.0f) { is_float = 0; break; } }
    }
    int base = bt*KVIS, cnt = 0;
    for (int v = 0; v < NV; v++) {
        int idx = bt*NP + valid_idx[v];
        int masked;
        if (is_int)        masked = (mi[idx] != 0);
        else if (is_float) masked = (mf[idx] != 0.0f);
        else               masked = (mb[idx] != 0);
        if (!masked) { if (cnt < KVIS) g_tokv[base+cnt] = v; cnt++; }
    }
}

// ---------------- patchify + patch embed + pos encodings ----------------
__global__ void __launch_bounds__(256) embed_kernel(
    const float* __restrict__ img, const int* __restrict__ valid_idx,
    const float* __restrict__ Wpe, const float* __restrict__ bpe,
    const float* __restrict__ spos)
{
    __shared__ float pix[16][PD];
    __shared__ float wsm[DD][27];
    __shared__ int sm_v[16], sm_t[16], sm_off[16];
    int tid = threadIdx.x;
    int m0 = blockIdx.x * 16;
    if (tid < 16) {
        int m = m0 + tid;
        int b = m / LL;
        int l = m - b*LL;
        int t = l / KVIS;
        int v = g_tokv[m];
        int patch = valid_idx[v];
        int hp = patch / NWP, wp = patch - hp*NWP;
        sm_v[tid] = v; sm_t[tid] = t;
        sm_off[tid] = ((b*TT + t)*HIMG + hp*PS)*WIMG + wp*PS;
    }
    __syncthreads();
    for (int j = tid; j < 16*PD; j += 256) {
        int tok = j / PD, pd = j - tok*PD;
        int ph = pd / PS, pw = pd - ph*PS;
        pix[tok][pd] = img[sm_off[tok] + ph*WIMG + pw];
    }
    float acc[16];
    #pragma unroll
    for (int i = 0; i < 16; i++) acc[i] = 0.f;
    for (int k0 = 0; k0 < PD; k0 += 25) {
        __syncthreads();
        for (int j = tid; j < DD*25; j += 256) {
            int dd = j / 25, kk = j - dd*25;
            wsm[dd][kk] = Wpe[dd*PD + k0 + kk];
        }
        __syncthreads();
        #pragma unroll
        for (int kk = 0; kk < 25; kk++) {
            float w = wsm[tid][kk];
            #pragma unroll
            for (int tok = 0; tok < 16; tok++)
                acc[tok] = fmaf(w, pix[tok][k0+kk], acc[tok]);
        }
    }
    int d = tid;
    float freq = expf((float)(d & ~1) * (-9.210340371976184f / 256.f));
    float pb = bpe[d];
    #pragma unroll
    for (int tok = 0; tok < 16; tok++) {
        float val = (float)sm_t[tok] * freq;
        float pe = (d & 1) ? cosf(val) : sinf(val);
        g_x[(m0+tok)*DD + d] = acc[tok] + pb + spos[sm_v[tok]*DD + d] + pe;
    }
}

// ---------------- one-time prep: weights -> hi/lo bf16, layer-major --------
__global__ void prep_weights_kernel(const float* __restrict__ Wqkv, const float* __restrict__ Wo,
                                    const float* __restrict__ W1, const float* __restrict__ W2)
{
    int i = blockIdx.x*blockDim.x + threadIdx.x;
    int layer = i / WLAYER;
    int r = i - layer*WLAYER;
    float v;
    if      (r < WOFS_O) v = Wqkv[layer*196608 + r];
    else if (r < WOFS_1) v = Wo[layer*65536 + r - WOFS_O];
    else if (r < WOFS_2) v = W1[layer*262144 + r - WOFS_1];
    else                 v = W2[layer*262144 + r - WOFS_2];
    __nv_bfloat16 hh = __float2bfloat16(v);
    g_wh[i] = hh;
    g_wl[i] = __float2bfloat16(v - __bfloat162float(hh));
}

// ---------------- x fp32 -> hi/lo bf16 (after embed only) ----------------
__global__ void cvt_x_kernel()
{
    int i = blockIdx.x*blockDim.x + threadIdx.x;   // over MM*DD/2
    float2 v = ((const float2*)g_x)[i];
    unsigned h, l; split2(v.x, v.y, h, l);
    ((unsigned*)g_xh)[i] = h;
    ((unsigned*)g_xl)[i] = l;
}

// ---------------- per-layer prep: qkv fp32 -> Q/K hi/lo + V^T hi/lo --------
__global__ void __launch_bounds__(256) prep_qkv_kernel()
{
    __shared__ float vs[32][33];
    int bh = blockIdx.y;
    int b = bh >> 3, h = bh & 7;
    int l0 = blockIdx.x * 32;
    int tid = threadIdx.x;
    const float* qbase = g_qkv + (size_t)b*LL*768 + h*32;

    #pragma unroll
    for (int m = 0; m < 2; m++) {
        #pragma unroll
        for (int it = 0; it < 2; it++) {
            int j = it*256 + tid;
            int l = l0 + (j >> 4), dp = j & 15;
            if (l < LL) {
                float2 v = *(const float2*)(qbase + (size_t)l*768 + m*256 + dp*2);
                if (m == 0) { v.x *= ASCALE; v.y *= ASCALE; }
                unsigned hw, lw; split2(v.x, v.y, hw, lw);
                size_t o = ((size_t)bh*LL + l)*16 + dp;
                if (m == 0) { ((unsigned*)g_qh)[o] = hw; ((unsigned*)g_ql)[o] = lw; }
                else        { ((unsigned*)g_kh)[o] = hw; ((unsigned*)g_kl)[o] = lw; }
            }
        }
    }
    {
        int l = l0 + (tid >> 3), dq = tid & 7;
        float4 v = make_float4(0.f,0.f,0.f,0.f);
        if (l < LL) v = *(const float4*)(qbase + (size_t)l*768 + 512 + dq*4);
        int ll = tid >> 3;
        vs[dq*4+0][ll] = v.x; vs[dq*4+1][ll] = v.y;
        vs[dq*4+2][ll] = v.z; vs[dq*4+3][ll] = v.w;
    }
    __syncthreads();
    {
        int d = tid >> 3, c = tid & 7;
        float f0 = vs[d][c*4+0], f1 = vs[d][c*4+1], f2 = vs[d][c*4+2], f3 = vs[d][c*4+3];
        unsigned h0, w0, h1, w1;
        split2(f0, f1, h0, w0);
        split2(f2, f3, h1, w1);
        size_t o = (((size_t)bh*32 + d)*LTP + l0 + c*4) >> 1;
        ((unsigned*)g_vth)[o]   = h0; ((unsigned*)g_vth)[o+1] = h1;
        ((unsigned*)g_vtl)[o]   = w0; ((unsigned*)g_vtl)[o+1] = w1;
    }
}

// ---------------- bf16-split tensor-core GEMM, 3-stage cp.async ring -------
// C[m,n] = sum_k A[m,k]*W[n,k] + bias[n].  Block 128x128, BK=16, 256 thr.
#define GSTR 24
#define GARR (128*GSTR)                 /* elements per array per stage */
#define GSTAGE (4*GARR)                 /* elements per stage */
#define GEMM_SMEM (3*GSTAGE*2)          /* 73728 bytes */

__global__ void __launch_bounds__(256,2) gemm_kernel(
    const __nv_bfloat16* __restrict__ Ahg, const __nv_bfloat16* __restrict__ Alg,
    const __nv_bfloat16* __restrict__ Whg, const __nv_bfloat16* __restrict__ Wlg,
    const float* __restrict__ bias,
    float* __restrict__ C, __nv_bfloat16* __restrict__ Ch, __nv_bfloat16* __restrict__ Cl,
    int Ndim, int Kdim, int relu, int outbf)
{
    extern __shared__ __align__(16) char smraw[];
    __nv_bfloat16* smb = (__nv_bfloat16*)smraw;
    uint32_t smb_u = sptr(smraw);
    int tid = threadIdx.x, lane = tid & 31, wid = tid >> 5;
    int wm = wid >> 1, wn = wid & 1;
    int m0 = blockIdx.x*128, n0 = blockIdx.y*128;

    const __nv_bfloat16* srcs[4] = {
        Ahg + (size_t)m0*Kdim, Alg + (size_t)m0*Kdim,
        Whg + (size_t)n0*Kdim, Wlg + (size_t)n0*Kdim };

    float acc[2][8][4];
    #pragma unroll
    for (int i=0;i<2;i++)
        #pragma unroll
        for (int j=0;j<8;j++)
            #pragma unroll
            for (int q=0;q<4;q++) acc[i][j][q]=0.f;

    int arow = wm*32 + (lane & 15);
    int akoff = (lane >> 4) << 3;
    int brow = wn*64 + ((lane >> 4) << 3) + (lane & 7);
    int bkoff = ((lane >> 3) & 1) << 3;

    // stage loader: 4 arrays x 128 rows x 2 chunks (16B) = 1024 cp16
    #define GEMM_ISSUE(s, k0) do { \
        uint32_t base_ = smb_u + (s)*GSTAGE*2; \
        _Pragma("unroll") \
        for (int it_ = 0; it_ < 4; it_++) { \
            int idx_ = it_*256 + tid; \
            int arr_ = idx_ >> 8, rem_ = idx_ & 255; \
            int row_ = rem_ >> 1, ch_ = rem_ & 1; \
            const void* gp_ = srcs[arr_] + (size_t)row_*Kdim + (k0) + ch_*8; \
            uint32_t dst_ = base_ + (arr_*GARR + row_*GSTR + ch_*8)*2; \
            cp16(dst_, gp_); \
        } \
    } while(0)

    GEMM_ISSUE(0, 0);  CP_COMMIT();
    GEMM_ISSUE(1, 16); CP_COMMIT();

    int NTK = Kdim >> 4;
    for (int t = 0; t < NTK; t++) {
        CP_WAIT1();
        __syncthreads();
        if (t + 2 < NTK) {
            int s = (t+2) % 3;
            GEMM_ISSUE(s, (t+2)*16);
        }
        CP_COMMIT();

        __nv_bfloat16* Ah = smb + (t%3)*GSTAGE;
        __nv_bfloat16* Al = Ah + GARR;
        __nv_bfloat16* Wh = Al + GARR;
        __nv_bfloat16* Wl = Wh + GARR;

        unsigned ah0[4], al0[4], ah1[4], al1[4];
        ldsm4(ah0[0],ah0[1],ah0[2],ah0[3], sptr(Ah + arow*GSTR + akoff));
        ldsm4(al0[0],al0[1],al0[2],al0[3], sptr(Al + arow*GSTR + akoff));
        ldsm4(ah1[0],ah1[1],ah1[2],ah1[3], sptr(Ah + (arow+16)*GSTR + akoff));
        ldsm4(al1[0],al1[1],al1[2],al1[3], sptr(Al + (arow+16)*GSTR + akoff));

        #pragma unroll
        for (int p = 0; p < 4; p++) {
            unsigned bh[4], bl[4];
            ldsm4(bh[0],bh[1],bh[2],bh[3], sptr(Wh + (brow + p*16)*GSTR + bkoff));
            ldsm4(bl[0],bl[1],bl[2],bl[3], sptr(Wl + (brow + p*16)*GSTR + bkoff));
            mma_bf16(acc[0][2*p],   ah0, bh[0], bh[1]);
            mma_bf16(acc[0][2*p],   ah0, bl[0], bl[1]);
            mma_bf16(acc[0][2*p],   al0, bh[0], bh[1]);
            mma_bf16(acc[0][2*p+1], ah0, bh[2], bh[3]);
            mma_bf16(acc[0][2*p+1], ah0, bl[2], bl[3]);
            mma_bf16(acc[0][2*p+1], al0, bh[2], bh[3]);
            mma_bf16(acc[1][2*p],   ah1, bh[0], bh[1]);
            mma_bf16(acc[1][2*p],   ah1, bl[0], bl[1]);
            mma_bf16(acc[1][2*p],   al1, bh[0], bh[1]);
            mma_bf16(acc[1][2*p+1], ah1, bh[2], bh[3]);
            mma_bf16(acc[1][2*p+1], ah1, bl[2], bl[3]);
            mma_bf16(acc[1][2*p+1], al1, bh[2], bh[3]);
        }
        __syncthreads();
    }

    // epilogue
    int r0 = lane >> 2;
    int c2 = (lane & 3) << 1;
    #pragma unroll
    for (int ma = 0; ma < 2; ma++) {
        #pragma unroll
        for (int na = 0; na < 8; na++) {
            int col = n0 + wn*64 + na*8 + c2;
            float2 bsv = *(const float2*)(bias + col);
            float v0 = acc[ma][na][0] + bsv.x;
            float v1 = acc[ma][na][1] + bsv.y;
            float v2 = acc[ma][na][2] + bsv.x;
            float v3 = acc[ma][na][3] + bsv.y;
            if (relu) {
                v0 = fmaxf(v0,0.f); v1 = fmaxf(v1,0.f);
                v2 = fmaxf(v2,0.f); v3 = fmaxf(v3,0.f);
            }
            int row = m0 + wm*32 + ma*16 + r0;
            if (outbf) {
                unsigned hw, lw;
                size_t o = ((size_t)row*Ndim + col) >> 1;
                split2(v0, v1, hw, lw);
                ((unsigned*)Ch)[o] = hw; ((unsigned*)Cl)[o] = lw;
                o = ((size_t)(row+8)*Ndim + col) >> 1;
                split2(v2, v3, hw, lw);
                ((unsigned*)Ch)[o] = hw; ((unsigned*)Cl)[o] = lw;
            } else {
                *(float2*)(C + (size_t)row*Ndim + col) = make_float2(v0, v1);
                *(float2*)(C + (size_t)(row+8)*Ndim + col) = make_float2(v2, v3);
            }
        }
    }
}

// ---------------- flash attention, 3-stage cp.async K/V pipeline ----------
// SMEM elements: Q hi/lo 2*128*40 = 10240; per stage Kh/Kl 2*2560 + Vh/Vl 2*2304 = 9728
#define AQ_ELEMS (2*128*40)
#define AKV_ELEMS 9728
#define ATT_SMEM ((AQ_ELEMS + 3*AKV_ELEMS)*2)

__global__ void __launch_bounds__(256,2) attn_kernel(__nv_bfloat16* __restrict__ outh,
                                                     __nv_bfloat16* __restrict__ outl)
{
    extern __shared__ __align__(16) char smraw[];
    __nv_bfloat16* smb = (__nv_bfloat16*)smraw;
    uint32_t smb_u = sptr(smraw);
    __nv_bfloat16* Qhs = smb;                 // [128][40]
    __nv_bfloat16* Qls = Qhs + 128*40;

    int tid = threadIdx.x, lane = tid & 31, wid = tid >> 5;
    int q0 = blockIdx.x * 128;
    int bh = blockIdx.y;
    int b = bh >> 3, h = bh & 7;

    // ---- stage loader: K (512 cp16) + V (512 cp16) ----
    #define ATT_ISSUE(s, k0t) do { \
        uint32_t sb_ = smb_u + (AQ_ELEMS + (s)*AKV_ELEMS)*2; \
        _Pragma("unroll") \
        for (int it_ = 0; it_ < 4; it_++) { \
            int idx_ = it_*256 + tid; \
            if (idx_ < 512) { \
                int bsel_ = idx_ >> 8, rem_ = idx_ & 255; \
                int r_ = rem_ >> 2, c_ = rem_ & 3; \
                int krow_ = (k0t) + r_; \
                int pred_ = (krow_ < LL); \
                int kc_ = pred_ ? krow_ : 0; \
                const __nv_bfloat16* src_ = (bsel_ ? g_kl : g_kh) + ((size_t)bh*LL + kc_)*32 + c_*8; \
                uint32_t dst_ = sb_ + (bsel_*2560 + r_*40 + c_*8)*2; \
                cp16p(dst_, src_, pred_); \
            } else { \
                int j_ = idx_ - 512; \
                int bsel_ = j_ >> 8, rem_ = j_ & 255; \
                int dd_ = rem_ >> 3, c_ = rem_ & 7; \
                const __nv_bfloat16* src_ = (bsel_ ? g_vtl : g_vth) + ((size_t)bh*32 + dd_)*LTP + (k0t) + c_*8; \
                uint32_t dst_ = sb_ + (5120 + bsel_*2304 + dd_*72 + c_*8)*2; \
                cp16(dst_, src_); \
            } \
        } \
    } while(0)

    // ---- Q copy via cp.async (grouped with stage 0) ----
    #pragma unroll
    for (int it = 0; it < 4; it++) {
        int idx = it*256 + tid;
        int bsel = idx >> 9;
        int rem = idx & 511;
        int r = rem >> 2, c = rem & 3;
        int qrow = q0 + r;
        int pred = (qrow < LL);
        int qc = pred ? qrow : 0;
        const __nv_bfloat16* src = (bsel ? g_ql : g_qh) + ((size_t)bh*LL + qc)*32 + c*8;
        uint32_t dst = smb_u + ((bsel ? 128*40 : 0) + r*40 + c*8)*2;
        cp16p(dst, src, pred);
    }
    ATT_ISSUE(0, 0);  CP_COMMIT();
    ATT_ISSUE(1, 64); CP_COMMIT();

    int arow = wid*16 + (lane & 15);
    int akoff = (lane >> 4) << 3;
    int brow = ((lane >> 4) << 3) + (lane & 7);
    int bkoff = ((lane >> 3) & 1) << 3;
    int c2 = (lane & 3) << 1;

    float sO[4][4];
    #pragma unroll
    for (int i=0;i<4;i++)
        #pragma unroll
        for (int j=0;j<4;j++) sO[i][j]=0.f;
    float mrow[2] = {-1e30f, -1e30f};
    float lrow[2] = {0.f, 0.f};

    for (int kt = 0; kt < 34; kt++) {
        int k0t = kt*64;
        CP_WAIT1();
        __syncthreads();
        if (kt + 2 < 34) {
            int s = (kt+2) % 3;
            ATT_ISSUE(s, (kt+2)*64);
        }
        CP_COMMIT();

        __nv_bfloat16* Khs = smb + AQ_ELEMS + (kt%3)*AKV_ELEMS;
        __nv_bfloat16* Kls = Khs + 2560;
        __nv_bfloat16* Vhs = Khs + 5120;
        __nv_bfloat16* Vls = Vhs + 2304;

        // ---- S = Q K^T ----
        float s[8][4];
        #pragma unroll
        for (int i=0;i<8;i++)
            #pragma unroll
            for (int j=0;j<4;j++) s[i][j]=0.f;
        #pragma unroll
        for (int ks = 0; ks < 2; ks++) {
            unsigned ah[4], al[4];
            ldsm4(ah[0],ah[1],ah[2],ah[3], sptr(Qhs + arow*40 + ks*16 + akoff));
            ldsm4(al[0],al[1],al[2],al[3], sptr(Qls + arow*40 + ks*16 + akoff));
            #pragma unroll
            for (int p = 0; p < 4; p++) {
                unsigned bhr[4], blr[4];
                ldsm4(bhr[0],bhr[1],bhr[2],bhr[3], sptr(Khs + (brow + p*16)*40 + ks*16 + bkoff));
                ldsm4(blr[0],blr[1],blr[2],blr[3], sptr(Kls + (brow + p*16)*40 + ks*16 + bkoff));
                mma_bf16(s[2*p],   ah, bhr[0], bhr[1]);
                mma_bf16(s[2*p],   ah, blr[0], blr[1]);
                mma_bf16(s[2*p],   al, bhr[0], bhr[1]);
                mma_bf16(s[2*p+1], ah, bhr[2], bhr[3]);
                mma_bf16(s[2*p+1], ah, blr[2], blr[3]);
                mma_bf16(s[2*p+1], al, bhr[2], bhr[3]);
            }
        }

        // ---- online softmax (scale pre-folded into Q) ----
        int tail = (k0t + 64 > LL);
        float fac[2];
        #pragma unroll
        for (int hf = 0; hf < 2; hf++) {
            float vmax = -1e30f;
            #pragma unroll
            for (int na = 0; na < 8; na++) {
                float v0 = s[na][2*hf];
                float v1 = s[na][2*hf+1];
                if (tail) {
                    if (k0t + na*8 + c2     >= LL) v0 = -1e30f;
                    if (k0t + na*8 + c2 + 1 >= LL) v1 = -1e30f;
                }
                s[na][2*hf] = v0; s[na][2*hf+1] = v1;
                vmax = fmaxf(vmax, fmaxf(v0, v1));
            }
            vmax = fmaxf(vmax, __shfl_xor_sync(0xffffffffu, vmax, 1));
            vmax = fmaxf(vmax, __shfl_xor_sync(0xffffffffu, vmax, 2));
            float mnew = fmaxf(mrow[hf], vmax);
            fac[hf] = __expf(mrow[hf] - mnew);
            mrow[hf] = mnew;
            float ps = 0.f;
            #pragma unroll
            for (int na = 0; na < 8; na++) {
                float p0 = __expf(s[na][2*hf]   - mnew);
                float p1 = __expf(s[na][2*hf+1] - mnew);
                s[na][2*hf] = p0; s[na][2*hf+1] = p1;
                ps += p0 + p1;
            }
            ps += __shfl_xor_sync(0xffffffffu, ps, 1);
            ps += __shfl_xor_sync(0xffffffffu, ps, 2);
            lrow[hf] = lrow[hf]*fac[hf] + ps;
        }

        // ---- pack P fragments ----
        unsigned pah[4][4], pal[4][4];
        #pragma unroll
        for (int ks = 0; ks < 4; ks++) {
            split2(s[2*ks][0],   s[2*ks][1],   pah[ks][0], pal[ks][0]);
            split2(s[2*ks][2],   s[2*ks][3],   pah[ks][1], pal[ks][1]);
            split2(s[2*ks+1][0], s[2*ks+1][1], pah[ks][2], pal[ks][2]);
            split2(s[2*ks+1][2], s[2*ks+1][3], pah[ks][3], pal[ks][3]);
        }

        // ---- rescale O ----
        #pragma unroll
        for (int na = 0; na < 4; na++) {
            sO[na][0] *= fac[0]; sO[na][1] *= fac[0];
            sO[na][2] *= fac[1]; sO[na][3] *= fac[1];
        }

        // ---- O += P V ----
        #pragma unroll
        for (int ks = 0; ks < 4; ks++) {
            #pragma unroll
            for (int p = 0; p < 2; p++) {
                unsigned bhr[4], blr[4];
                ldsm4(bhr[0],bhr[1],bhr[2],bhr[3], sptr(Vhs + (brow + p*16)*72 + ks*16 + bkoff));
                ldsm4(blr[0],blr[1],blr[2],blr[3], sptr(Vls + (brow + p*16)*72 + ks*16 + bkoff));
                mma_bf16(sO[2*p],   pah[ks], bhr[0], bhr[1]);
                mma_bf16(sO[2*p],   pah[ks], blr[0], blr[1]);
                mma_bf16(sO[2*p],   pal[ks], bhr[0], bhr[1]);
                mma_bf16(sO[2*p+1], pah[ks], bhr[2], bhr[3]);
                mma_bf16(sO[2*p+1], pah[ks], blr[2], blr[3]);
                mma_bf16(sO[2*p+1], pal[ks], bhr[2], bhr[3]);
            }
        }
    }

    // ---- normalize + store hi/lo bf16 ----
    int r0 = lane >> 2;
    float inv0 = 1.f / lrow[0];
    float inv1 = 1.f / lrow[1];
    #pragma unroll
    for (int na = 0; na < 4; na++) {
        int col = h*DH + na*8 + c2;
        int qrow = q0 + wid*16 + r0;
        unsigned hw, lw;
        if (qrow < LL) {
            split2(sO[na][0]*inv0, sO[na][1]*inv0, hw, lw);
            size_t o = (((size_t)(b*LL + qrow))*DD + col) >> 1;
            ((unsigned*)outh)[o] = hw; ((unsigned*)outl)[o] = lw;
        }
        if (qrow + 8 < LL) {
            split2(sO[na][2]*inv1, sO[na][3]*inv1, hw, lw);
            size_t o = (((size_t)(b*LL + qrow + 8))*DD + col) >> 1;
            ((unsigned*)outh)[o] = hw; ((unsigned*)outl)[o] = lw;
        }
    }
}

// ---------------- residual add + LayerNorm (warp/row) + optional bf16 split -
__global__ void __launch_bounds__(256) add_ln_kernel(
    const float* __restrict__ x, const float* __restrict__ y,
    const float* __restrict__ gam, const float* __restrict__ bet,
    float* __restrict__ out, __nv_bfloat16* __restrict__ oh, __nv_bfloat16* __restrict__ ol,
    int doadd)
{
    int warp = threadIdx.x >> 5, lane = threadIdx.x & 31;
    int row = blockIdx.x*8 + warp;
    const float* xr = x + (size_t)row*DD + lane*8;
    float v[8];
    float4 va = *(const float4*)(xr);
    float4 vb = *(const float4*)(xr + 4);
    v[0]=va.x; v[1]=va.y; v[2]=va.z; v[3]=va.w;
    v[4]=vb.x; v[5]=vb.y; v[6]=vb.z; v[7]=vb.w;
    if (doadd) {
        const float* yr = y + (size_t)row*DD + lane*8;
        float4 ya = *(const float4*)(yr);
        float4 yb = *(const float4*)(yr + 4);
        v[0]+=ya.x; v[1]+=ya.y; v[2]+=ya.z; v[3]+=ya.w;
        v[4]+=yb.x; v[5]+=yb.y; v[6]+=yb.z; v[7]+=yb.w;
    }
    float s = 0.f;
    #pragma unroll
    for (int i=0;i<8;i++) s += v[i];
    #pragma unroll
    for (int off=16; off; off>>=1) s += __shfl_xor_sync(0xffffffffu, s, off);
    float mean = s * (1.f/DD);
    float s2 = 0.f;
    #pragma unroll
    for (int i=0;i<8;i++) { v[i] -= mean; s2 += v[i]*v[i]; }
    #pragma unroll
    for (int off=16; off; off>>=1) s2 += __shfl_xor_sync(0xffffffffu, s2, off);
    float rstd = rsqrtf(s2 * (1.f/DD) + 1e-5f);
    const float* gp = gam + lane*8;
    const float* bp = bet + lane*8;
    float4 ga = *(const float4*)(gp);
    float4 gb = *(const float4*)(gp+4);
    float4 ba = *(const float4*)(bp);
    float4 bb = *(const float4*)(bp+4);
    float g[8] = {ga.x,ga.y,ga.z,ga.w,gb.x,gb.y,gb.z,gb.w};
    float be[8] = {ba.x,ba.y,ba.z,ba.w,bb.x,bb.y,bb.z,bb.w};
    float o[8];
    #pragma unroll
    for (int i=0;i<8;i++) o[i] = v[i]*rstd*g[i] + be[i];
    float* op = out + (size_t)row*DD + lane*8;
    *(float4*)(op)   = make_float4(o[0],o[1],o[2],o[3]);
    *(float4*)(op+4) = make_float4(o[4],o[5],o[6],o[7]);
    if (oh) {
        unsigned hw[4], lw[4];
        split2(o[0],o[1],hw[0],lw[0]);
        split2(o[2],o[3],hw[1],lw[1]);
        split2(o[4],o[5],hw[2],lw[2]);
        split2(o[6],o[7],hw[3],lw[3]);
        size_t ob = ((size_t)row*DD + lane*8) >> 1;
        *(uint4*)((unsigned*)oh + ob) = make_uint4(hw[0],hw[1],hw[2],hw[3]);
        *(uint4*)((unsigned*)ol + ob) = make_uint4(lw[0],lw[1],lw[2],lw[3]);
    }
}

// ---------------- launch ----------------
extern "C" void kernel_launch(void* const* d_in, const int* in_sizes, int n_in,
                              void* d_out, int out_size)
{
    const float* x_img          = (const float*)d_in[0];
    const void*  pmask          = (const void*)d_in[1];
    const int*   valid_idx      = (const int*)d_in[2];
    const float* pe_w           = (const float*)d_in[3];
    const float* pe_b           = (const float*)d_in[4];
    const float* spos           = (const float*)d_in[5];
    const float* Wqkv           = (const float*)d_in[6];
    const float* bqkv           = (const float*)d_in[7];
    const float* Wo             = (const float*)d_in[8];
    const float* bo             = (const float*)d_in[9];
    const float* ln1s           = (const float*)d_in[10];
    const float* ln1b           = (const float*)d_in[11];
    const float* W1             = (const float*)d_in[12];
    const float* b1             = (const float*)d_in[13];
    const float* W2             = (const float*)d_in[14];
    const float* b2             = (const float*)d_in[15];
    const float* ln2s           = (const float*)d_in[16];
    const float* ln2b           = (const float*)d_in[17];
    const float* nfs            = (const float*)d_in[18];
    const float* nfb            = (const float*)d_in[19];
    float* out = (float*)d_out;

    float *px, *py;
    __nv_bfloat16 *pxh, *pxl, *path, *patl, *pffh, *pffl, *pwh, *pwl;
    cudaGetSymbolAddress((void**)&px,   g_x);
    cudaGetSymbolAddress((void**)&py,   g_y);
    cudaGetSymbolAddress((void**)&pxh,  g_xh);
    cudaGetSymbolAddress((void**)&pxl,  g_xl);
    cudaGetSymbolAddress((void**)&path, g_atth);
    cudaGetSymbolAddress((void**)&patl, g_attl);
    cudaGetSymbolAddress((void**)&pffh, g_ffh);
    cudaGetSymbolAddress((void**)&pffl, g_ffl);
    cudaGetSymbolAddress((void**)&pwh,  g_wh);
    cudaGetSymbolAddress((void**)&pwl,  g_wl);
    float* pqkv;
    cudaGetSymbolAddress((void**)&pqkv, g_qkv);

    cudaFuncSetAttribute(attn_kernel, cudaFuncAttributeMaxDynamicSharedMemorySize, ATT_SMEM);
    cudaFuncSetAttribute(gemm_kernel, cudaFuncAttributeMaxDynamicSharedMemorySize, GEMM_SMEM);

    prep_weights_kernel<<<WTOTAL/256, 256>>>(Wqkv, Wo, W1, W2);
    build_vis_kernel<<<(BB*TT+255)/256, 256>>>(pmask, valid_idx);
    embed_kernel<<<MM/16, 256>>>(x_img, valid_idx, pe_w, pe_b, spos);
    cvt_x_kernel<<<MM*DD/512, 256>>>();

    for (int i = 0; i < NLAYERS; i++) {
        const __nv_bfloat16* wh = pwh + (size_t)i*WLAYER;
        const __nv_bfloat16* wl = pwl + (size_t)i*WLAYER;
        gemm_kernel<<<dim3(MM/128, 6), 256, GEMM_SMEM>>>(
            pxh, pxl, wh + WOFS_QKV, wl + WOFS_QKV, bqkv + i*768,
            pqkv, nullptr, nullptr, 768, 256, 0, 0);
        prep_qkv_kernel<<<dim3(68, BB*NHEAD), 256>>>();
        attn_kernel<<<dim3(17, BB*NHEAD), 256, ATT_SMEM>>>(path, patl);
        gemm_kernel<<<dim3(MM/128, 2), 256, GEMM_SMEM>>>(
            path, patl, wh + WOFS_O, wl + WOFS_O, bo + i*256,
            py, nullptr, nullptr, 256, 256, 0, 0);
        add_ln_kernel<<<MM/8, 256>>>(px, py, ln1s + i*DD, ln1b + i*DD, px, pxh, pxl, 1);
        gemm_kernel<<<dim3(MM/128, 8), 256, GEMM_SMEM>>>(
            pxh, pxl, wh + WOFS_1, wl + WOFS_1, b1 + i*DFF,
            nullptr, pffh, pffl, 1024, 256, 1, 1);
        gemm_kernel<<<dim3(MM/128, 2), 256, GEMM_SMEM>>>(
            pffh, pffl, wh + WOFS_2, wl + WOFS_2, b2 + i*256,
            py, nullptr, nullptr, 256, 1024, 0, 0);
        add_ln_kernel<<<MM/8, 256>>>(px, py, ln2s + i*DD, ln2b + i*DD, px, pxh, pxl, 1);
    }
    add_ln_kernel<<<MM/8, 256>>>(px, px, nfs, nfb, out, nullptr, nullptr, 0);
}